// round 9
// baseline (speedup 1.0000x reference)
#include <cuda_runtime.h>
#include <cuda_fp16.h>
#include <cstdint>

#define EMBED 256
#define HEADS 4
#define HDIM  64
#define BATCH 4
#define SQL   512
#define SKL   512
#define MTOT  (BATCH*SQL)   /* 2048 */

// Scratch (allocation-free rule: __device__ globals)
__device__ __half g_Qh[MTOT*EMBED];   // Q projection, half
__device__ __half g_Kh[MTOT*EMBED];   // K projection, half
__device__ float  g_V [MTOT*EMBED];   // V projection, f32
__device__ float  g_att[MTOT*EMBED];  // attended, f32

__device__ __forceinline__ __half2 htanh2(__half2 x) {
    unsigned int xi = *reinterpret_cast<unsigned int*>(&x);
    unsigned int yi;
    asm("tanh.approx.f16x2 %0, %1;" : "=r"(yi) : "r"(xi));
    return *reinterpret_cast<__half2*>(&yi);
}
__device__ __forceinline__ float sumh2(__half2 h) {
    float2 f = __half22float2(h);
    return f.x + f.y;
}
__device__ __forceinline__ __half2 u2h(unsigned int u) {
    return *reinterpret_cast<__half2*>(&u);
}
__device__ __forceinline__ void cp_async16(void* smem_dst, const void* gsrc) {
    unsigned int saddr = (unsigned int)__cvta_generic_to_shared(smem_dst);
    asm volatile("cp.async.cg.shared.global [%0], [%1], 16;\n" :: "r"(saddr), "l"(gsrc));
}
__device__ __forceinline__ void cp_commit() {
    asm volatile("cp.async.commit_group;\n");
}
template<int N>
__device__ __forceinline__ void cp_wait() {
    asm volatile("cp.async.wait_group %0;\n" :: "n"(N));
}

// ---------------------------------------------------------------------------
// C[M,N] = A[M,K] @ W[N,K]^T + bias[N]   (torch Linear semantics)
// 64x64 tile, BK=16, 256 threads, 4x4 micro-tile, double-buffered smem.
// grid.z selects one of up to 3 problems. If Hz != nullptr for the selected
// problem, output is written as half to Hz instead of f32 to Cz.
// ---------------------------------------------------------------------------
__global__ __launch_bounds__(256) void gemm_bias3_kernel(
    const float* __restrict__ A0, const float* __restrict__ A1, const float* __restrict__ A2,
    const float* __restrict__ W0, const float* __restrict__ W1, const float* __restrict__ W2,
    const float* __restrict__ b0, const float* __restrict__ b1, const float* __restrict__ b2,
    float* __restrict__ C0, float* __restrict__ C1, float* __restrict__ C2,
    __half* __restrict__ H0, __half* __restrict__ H1, __half* __restrict__ H2,
    int M, int N, int K)
{
    const float* A; const float* W; const float* bias; float* C; __half* H;
    if (blockIdx.z == 0)      { A = A0; W = W0; bias = b0; C = C0; H = H0; }
    else if (blockIdx.z == 1) { A = A1; W = W1; bias = b1; C = C1; H = H1; }
    else                      { A = A2; W = W2; bias = b2; C = C2; H = H2; }

    __shared__ float As[2][16][68];
    __shared__ float Ws[2][16][68];
    const int tid = threadIdx.x;
    const int tx  = tid & 15;        // n direction
    const int ty  = tid >> 4;        // m direction
    const int n0  = blockIdx.x * 64;
    const int m0  = blockIdx.y * 64;

    const int lr = tid >> 2;          // 0..63 row in tile
    const int lc = (tid & 3) << 2;    // 0,4,8,12 k offset
    const float* Ag = A + (size_t)(m0 + lr) * K + lc;
    const float* Wg = W + (size_t)(n0 + lr) * K + lc;

    float a00=0,a01=0,a02=0,a03=0, a10=0,a11=0,a12=0,a13=0;
    float a20=0,a21=0,a22=0,a23=0, a30=0,a31=0,a32=0,a33=0;

    float4 av = *(const float4*)(Ag);
    float4 wv = *(const float4*)(Wg);
    int buf = 0;

    for (int k0 = 0; k0 < K; k0 += 16) {
        As[buf][lc+0][lr] = av.x; As[buf][lc+1][lr] = av.y;
        As[buf][lc+2][lr] = av.z; As[buf][lc+3][lr] = av.w;
        Ws[buf][lc+0][lr] = wv.x; Ws[buf][lc+1][lr] = wv.y;
        Ws[buf][lc+2][lr] = wv.z; Ws[buf][lc+3][lr] = wv.w;
        __syncthreads();
        if (k0 + 16 < K) {
            av = *(const float4*)(Ag + k0 + 16);
            wv = *(const float4*)(Wg + k0 + 16);
        }
        #pragma unroll
        for (int k = 0; k < 16; k++) {
            float4 a = *(const float4*)&As[buf][k][ty*4];
            float4 w = *(const float4*)&Ws[buf][k][tx*4];
            a00 += a.x*w.x; a01 += a.x*w.y; a02 += a.x*w.z; a03 += a.x*w.w;
            a10 += a.y*w.x; a11 += a.y*w.y; a12 += a.y*w.z; a13 += a.y*w.w;
            a20 += a.z*w.x; a21 += a.z*w.y; a22 += a.z*w.z; a23 += a.z*w.w;
            a30 += a.w*w.x; a31 += a.w*w.y; a32 += a.w*w.z; a33 += a.w*w.w;
        }
        buf ^= 1;
    }

    const float4 bb = *(const float4*)&bias[n0 + tx*4];
    float r0x=a00+bb.x, r0y=a01+bb.y, r0z=a02+bb.z, r0w=a03+bb.w;
    float r1x=a10+bb.x, r1y=a11+bb.y, r1z=a12+bb.z, r1w=a13+bb.w;
    float r2x=a20+bb.x, r2y=a21+bb.y, r2z=a22+bb.z, r2w=a23+bb.w;
    float r3x=a30+bb.x, r3y=a31+bb.y, r3z=a32+bb.z, r3w=a33+bb.w;

    if (H) {
        __half* Hp = H + (size_t)(m0 + ty*4) * N + n0 + tx*4;
        __half2 p0, p1;
        p0 = __floats2half2_rn(r0x, r0y); p1 = __floats2half2_rn(r0z, r0w);
        *(uint2*)(Hp)       = make_uint2(*(unsigned int*)&p0, *(unsigned int*)&p1);
        p0 = __floats2half2_rn(r1x, r1y); p1 = __floats2half2_rn(r1z, r1w);
        *(uint2*)(Hp + N)   = make_uint2(*(unsigned int*)&p0, *(unsigned int*)&p1);
        p0 = __floats2half2_rn(r2x, r2y); p1 = __floats2half2_rn(r2z, r2w);
        *(uint2*)(Hp + 2*N) = make_uint2(*(unsigned int*)&p0, *(unsigned int*)&p1);
        p0 = __floats2half2_rn(r3x, r3y); p1 = __floats2half2_rn(r3z, r3w);
        *(uint2*)(Hp + 3*N) = make_uint2(*(unsigned int*)&p0, *(unsigned int*)&p1);
    } else {
        float* Cp = C + (size_t)(m0 + ty*4) * N + n0 + tx*4;
        float4 o;
        o.x=r0x; o.y=r0y; o.z=r0z; o.w=r0w; *(float4*)(Cp)       = o;
        o.x=r1x; o.y=r1y; o.z=r1z; o.w=r1w; *(float4*)(Cp + N)   = o;
        o.x=r2x; o.y=r2y; o.z=r2z; o.w=r2w; *(float4*)(Cp + 2*N) = o;
        o.x=r3x; o.y=r3y; o.z=r3z; o.w=r3w; *(float4*)(Cp + 3*N) = o;
    }
}

// ---------------------------------------------------------------------------
// Fused additive-attention kernel, v6b: cp.async 3-deep pipelines.
// (v6 + fix: Q/v inner-loop segments indexed logically [db]; only the K read
//  address is swizzled — store swizzle and read swizzle cancel to segment db.)
// ---------------------------------------------------------------------------
#define SCT_PITCH 20
#define CKK 32
#define NCHK (SKL/CKK)    /* 16 */
#define CKV 16
#define NCHV (SKL/CKV)    /* 32 */
#define UNION_FLOATS 3072 /* 3 x 4096 B */
#define ATTN_SMEM_FLOATS (SKL*SCT_PITCH + UNION_FLOATS + 512 + 32)

__global__ __launch_bounds__(256, 4) void attn_kernel(
    const float* __restrict__ vparam, float* __restrict__ attn_out)
{
    extern __shared__ float smem[];
    float*  scT = smem;                           // [512][20] scores/probs, k-major
    float*  uni = scT + SKL*SCT_PITCH;            // union staging region
    __half* qh  = (__half*)(uni + UNION_FLOATS);  // [16][64] half Q
    __half* vh  = qh + 16*64;                     // [64] half v

    const int tid  = threadIdx.x;
    const int lane = tid & 31;
    const int warp = tid >> 5;
    const int b  = blockIdx.z;
    const int h  = blockIdx.y;
    const int q0t = blockIdx.x << 4;

    // ---- stage v and Q rows (half) ----
    if (tid < 64) vh[tid] = __float2half(vparam[h*HDIM + tid]);
    {
        int row = tid >> 4;
        int seg = tid & 15;               // 8B segment
        const uint2* src = (const uint2*)&g_Qh[((size_t)(b*SQL + q0t + row))*EMBED + h*HDIM + seg*4];
        *(uint2*)&qh[row*64 + seg*4] = *src;
    }

    const float scale = 0.125f;   // 1/sqrt(64)
    const int qa = warp*2;
    const int qb = qa + 1;

    // ================= score phase: 16 chunks of 32 k-rows =================
    {
        __half* kb[3] = { (__half*)uni, (__half*)uni + 2048, (__half*)uni + 4096 };
        const int krow = tid >> 3;        // 0..31
        const int kseg = tid & 7;         // 16B segment of 128B row
        const int sseg = kseg ^ (krow & 7);   // swizzled segment
        const __half* Kg = &g_Kh[((size_t)(b*SKL))*EMBED + h*HDIM];

        // prime chunks 0,1
        #pragma unroll
        for (int c = 0; c < 2; c++) {
            cp_async16(&kb[c][krow*64 + sseg*8],
                       Kg + ((size_t)(c*CKK + krow))*EMBED + kseg*8);
            cp_commit();
        }

        for (int c = 0; c < NCHK; c++) {
            if (c + 1 < NCHK) cp_wait<1>(); else cp_wait<0>();
            __syncthreads();
            if (c + 2 < NCHK) {
                cp_async16(&kb[(c+2)%3][krow*64 + sseg*8],
                           Kg + ((size_t)((c+2)*CKK + krow))*EMBED + kseg*8);
                cp_commit();
            }

            const __half* kr = kb[c%3] + lane*64;       // this lane's k-row
            const uint4* qa4p = (const uint4*)&qh[qa*64];
            const uint4* qb4p = (const uint4*)&qh[qb*64];
            const uint4* vv4p = (const uint4*)vh;
            const int sw = lane & 7;

            __half2 z = __float2half2_rn(0.f);
            __half2 accA0=z, accA1=z, accB0=z, accB1=z;

            #pragma unroll
            for (int db = 0; db < 8; db++) {
                // physical slot db^sw holds logical segment (db^sw)^sw = db
                uint4 k4 = *(const uint4*)(kr + ((db ^ sw) * 8));
                uint4 qa4 = qa4p[db];     // logical segment db (broadcast)
                uint4 qb4 = qb4p[db];
                uint4 vv4 = vv4p[db];

                __half2 k0=u2h(k4.x), k1=u2h(k4.y), k2=u2h(k4.z), k3=u2h(k4.w);
                __half2 qa0=u2h(qa4.x), qa1=u2h(qa4.y), qa2=u2h(qa4.z), qa3=u2h(qa4.w);
                __half2 qb0=u2h(qb4.x), qb1=u2h(qb4.y), qb2=u2h(qb4.z), qb3=u2h(qb4.w);
                __half2 v0=u2h(vv4.x), v1=u2h(vv4.y), v2=u2h(vv4.z), v3=u2h(vv4.w);

                accA0 = __hfma2(v0, htanh2(__hadd2(qa0, k0)), accA0);
                accB0 = __hfma2(v0, htanh2(__hadd2(qb0, k0)), accB0);
                accA1 = __hfma2(v1, htanh2(__hadd2(qa1, k1)), accA1);
                accB1 = __hfma2(v1, htanh2(__hadd2(qb1, k1)), accB1);
                accA0 = __hfma2(v2, htanh2(__hadd2(qa2, k2)), accA0);
                accB0 = __hfma2(v2, htanh2(__hadd2(qb2, k2)), accB0);
                accA1 = __hfma2(v3, htanh2(__hadd2(qa3, k3)), accA1);
                accB1 = __hfma2(v3, htanh2(__hadd2(qb3, k3)), accB1);
            }

            scT[(c*CKK + lane)*SCT_PITCH + qa] = (sumh2(accA0) + sumh2(accA1)) * scale;
            scT[(c*CKK + lane)*SCT_PITCH + qb] = (sumh2(accB0) + sumh2(accB1)) * scale;
        }
    }
    __syncthreads();   // all scores written, all K staging reads done

    // ---- prime V chunks 0,1 (overlaps softmax) ----
    {
        float* vb0 = uni;
        float* vb1 = uni + 1024;
        const int vrow = tid >> 4;        // 0..15
        const int vseg = tid & 15;        // 16B segment of 256B row
        const float* Vg = &g_V[((size_t)(b*SKL))*EMBED + h*HDIM];
        cp_async16(&vb0[vrow*64 + vseg*4], Vg + ((size_t)(0*CKV + vrow))*EMBED + vseg*4);
        cp_commit();
        cp_async16(&vb1[vrow*64 + vseg*4], Vg + ((size_t)(1*CKV + vrow))*EMBED + vseg*4);
        cp_commit();
    }

    // ---------------- softmax (each warp: 2 rows of 512) ----------------
    #pragma unroll
    for (int qq = 0; qq < 2; qq++) {
        const int q = qa + qq;
        float x[16];
        #pragma unroll
        for (int j = 0; j < 16; j++) x[j] = scT[(lane + 32*j)*SCT_PITCH + q];
        float m = -1e30f;
        #pragma unroll
        for (int j = 0; j < 16; j++) m = fmaxf(m, x[j]);
        #pragma unroll
        for (int o = 16; o; o >>= 1) m = fmaxf(m, __shfl_xor_sync(0xffffffffu, m, o));
        float s = 0.f;
        #pragma unroll
        for (int j = 0; j < 16; j++) { x[j] = __expf(x[j] - m); s += x[j]; }
        #pragma unroll
        for (int o = 16; o; o >>= 1) s += __shfl_xor_sync(0xffffffffu, s, o);
        const float r = 1.0f / s;
        float* arow = attn_out + ((size_t)((b*HEADS + h)*SQL + q0t + q))*SKL;
        #pragma unroll
        for (int j = 0; j < 16; j++) {
            float p = x[j] * r;
            scT[(lane + 32*j)*SCT_PITCH + q] = p;
            arow[lane + 32*j] = p;
        }
    }

    // ================= AV phase: 32 chunks of 16 k-rows =================
    {
        float* vb[3] = { uni, uni + 1024, uni + 2048 };
        const int vrow = tid >> 4;
        const int vseg = tid & 15;
        const float* Vg = &g_V[((size_t)(b*SKL))*EMBED + h*HDIM];

        const int g  = lane >> 3;            // q-group: q = 4g..4g+3
        const int dl = warp*8 + (lane & 7);  // this thread's d
        float a0=0.f, a1=0.f, a2=0.f, a3=0.f;

        for (int c = 0; c < NCHV; c++) {
            if (c + 1 < NCHV) cp_wait<1>(); else cp_wait<0>();
            __syncthreads();
            if (c + 2 < NCHV) {
                cp_async16(&vb[(c+2)%3][vrow*64 + vseg*4],
                           Vg + ((size_t)((c+2)*CKV + vrow))*EMBED + vseg*4);
                cp_commit();
            }

            const float* pb = &scT[(c*CKV)*SCT_PITCH + 4*g];
            const float* vbp = vb[c%3] + dl;
            #pragma unroll
            for (int kp = 0; kp < CKV; kp++) {
                float4 p = *(const float4*)(pb + kp*SCT_PITCH);
                float  v = vbp[kp*64];
                a0 += p.x*v; a1 += p.y*v; a2 += p.z*v; a3 += p.w*v;
            }
        }

        float* abase = &g_att[((size_t)(b*SQL + q0t + 4*g))*EMBED + h*HDIM + dl];
        abase[0]       = a0;
        abase[EMBED]   = a1;
        abase[2*EMBED] = a2;
        abase[3*EMBED] = a3;
    }
}

// ---------------------------------------------------------------------------
extern "C" void kernel_launch(void* const* d_in, const int* in_sizes, int n_in,
                              void* d_out, int out_size)
{
    (void)in_sizes; (void)n_in; (void)out_size;
    const float* query = (const float*)d_in[0];
    const float* key_  = (const float*)d_in[1];
    const float* value = (const float*)d_in[2];
    const float* Wq = (const float*)d_in[3];
    const float* bq = (const float*)d_in[4];
    const float* Wk = (const float*)d_in[5];
    const float* bk = (const float*)d_in[6];
    const float* Wv = (const float*)d_in[7];
    const float* bv = (const float*)d_in[8];
    const float* vp = (const float*)d_in[9];
    const float* Wo = (const float*)d_in[10];
    const float* bo = (const float*)d_in[11];

    float* out  = (float*)d_out;                 // [B, SQ, EMBED]
    float* attn = out + (size_t)MTOT * EMBED;    // [B, H, SQ, SK]

    __half *gQh, *gKh;
    float *gV, *gA;
    cudaGetSymbolAddress((void**)&gQh, g_Qh);
    cudaGetSymbolAddress((void**)&gKh, g_Kh);
    cudaGetSymbolAddress((void**)&gV,  g_V);
    cudaGetSymbolAddress((void**)&gA,  g_att);

    const int smem_bytes = ATTN_SMEM_FLOATS * (int)sizeof(float);
    cudaFuncSetAttribute(attn_kernel, cudaFuncAttributeMaxDynamicSharedMemorySize, smem_bytes);

    dim3 ggrid3(EMBED/64, MTOT/64, 3);   // (4, 32, 3)
    gemm_bias3_kernel<<<ggrid3, 256>>>(query, key_, value,
                                       Wq, Wk, Wv,
                                       bq, bk, bv,
                                       nullptr, nullptr, gV,
                                       gQh, gKh, nullptr,
                                       MTOT, EMBED, EMBED);

    dim3 agrid(SQL/16, HEADS, BATCH);  // (32, 4, 4)
    attn_kernel<<<agrid, 256, smem_bytes>>>(vp, attn);

    dim3 ggrid(EMBED/64, MTOT/64, 1);
    gemm_bias3_kernel<<<ggrid, 256>>>(gA, gA, gA,
                                      Wo, Wo, Wo,
                                      bo, bo, bo,
                                      out, out, out,
                                      nullptr, nullptr, nullptr,
                                      MTOT, EMBED, EMBED);
}

// round 10
// speedup vs baseline: 1.0273x; 1.0273x over previous
#include <cuda_runtime.h>
#include <cuda_fp16.h>
#include <cstdint>

#define EMBED 256
#define HEADS 4
#define HDIM  64
#define BATCH 4
#define SQL   512
#define SKL   512
#define MTOT  (BATCH*SQL)   /* 2048 */

// Scratch (allocation-free rule: __device__ globals)
__device__ __half g_Qh[MTOT*EMBED];   // Q projection, half
__device__ __half g_Kh[MTOT*EMBED];   // K projection, half
__device__ float  g_V [MTOT*EMBED];   // V projection, f32
__device__ float  g_att[MTOT*EMBED];  // attended, f32

__device__ __forceinline__ __half2 htanh2(__half2 x) {
    unsigned int xi = *reinterpret_cast<unsigned int*>(&x);
    unsigned int yi;
    asm("tanh.approx.f16x2 %0, %1;" : "=r"(yi) : "r"(xi));
    return *reinterpret_cast<__half2*>(&yi);
}
__device__ __forceinline__ float sumh2(__half2 h) {
    float2 f = __half22float2(h);
    return f.x + f.y;
}
__device__ __forceinline__ __half2 u2h(unsigned int u) {
    return *reinterpret_cast<__half2*>(&u);
}
__device__ __forceinline__ void cp_async16_ca(void* smem_dst, const void* gsrc) {
    unsigned int saddr = (unsigned int)__cvta_generic_to_shared(smem_dst);
    asm volatile("cp.async.ca.shared.global [%0], [%1], 16;\n" :: "r"(saddr), "l"(gsrc));
}
__device__ __forceinline__ void cp_commit() {
    asm volatile("cp.async.commit_group;\n");
}
template<int N>
__device__ __forceinline__ void cp_wait() {
    asm volatile("cp.async.wait_group %0;\n" :: "n"(N));
}

// ---------------------------------------------------------------------------
// C[M,N] = A[M,K] @ W[N,K]^T + bias[N]  (torch Linear). grid.z picks problem;
// Hz != nullptr -> write half to Hz, else f32 to Cz.
// ---------------------------------------------------------------------------
__global__ __launch_bounds__(256) void gemm_bias3_kernel(
    const float* __restrict__ A0, const float* __restrict__ A1, const float* __restrict__ A2,
    const float* __restrict__ W0, const float* __restrict__ W1, const float* __restrict__ W2,
    const float* __restrict__ b0, const float* __restrict__ b1, const float* __restrict__ b2,
    float* __restrict__ C0, float* __restrict__ C1, float* __restrict__ C2,
    __half* __restrict__ H0, __half* __restrict__ H1, __half* __restrict__ H2,
    int M, int N, int K)
{
    const float* A; const float* W; const float* bias; float* C; __half* H;
    if (blockIdx.z == 0)      { A = A0; W = W0; bias = b0; C = C0; H = H0; }
    else if (blockIdx.z == 1) { A = A1; W = W1; bias = b1; C = C1; H = H1; }
    else                      { A = A2; W = W2; bias = b2; C = C2; H = H2; }

    __shared__ float As[2][16][68];
    __shared__ float Ws[2][16][68];
    const int tid = threadIdx.x;
    const int tx  = tid & 15;
    const int ty  = tid >> 4;
    const int n0  = blockIdx.x * 64;
    const int m0  = blockIdx.y * 64;

    const int lr = tid >> 2;
    const int lc = (tid & 3) << 2;
    const float* Ag = A + (size_t)(m0 + lr) * K + lc;
    const float* Wg = W + (size_t)(n0 + lr) * K + lc;

    float a00=0,a01=0,a02=0,a03=0, a10=0,a11=0,a12=0,a13=0;
    float a20=0,a21=0,a22=0,a23=0, a30=0,a31=0,a32=0,a33=0;

    float4 av = *(const float4*)(Ag);
    float4 wv = *(const float4*)(Wg);
    int buf = 0;

    for (int k0 = 0; k0 < K; k0 += 16) {
        As[buf][lc+0][lr] = av.x; As[buf][lc+1][lr] = av.y;
        As[buf][lc+2][lr] = av.z; As[buf][lc+3][lr] = av.w;
        Ws[buf][lc+0][lr] = wv.x; Ws[buf][lc+1][lr] = wv.y;
        Ws[buf][lc+2][lr] = wv.z; Ws[buf][lc+3][lr] = wv.w;
        __syncthreads();
        if (k0 + 16 < K) {
            av = *(const float4*)(Ag + k0 + 16);
            wv = *(const float4*)(Wg + k0 + 16);
        }
        #pragma unroll
        for (int k = 0; k < 16; k++) {
            float4 a = *(const float4*)&As[buf][k][ty*4];
            float4 w = *(const float4*)&Ws[buf][k][tx*4];
            a00 += a.x*w.x; a01 += a.x*w.y; a02 += a.x*w.z; a03 += a.x*w.w;
            a10 += a.y*w.x; a11 += a.y*w.y; a12 += a.y*w.z; a13 += a.y*w.w;
            a20 += a.z*w.x; a21 += a.z*w.y; a22 += a.z*w.z; a23 += a.z*w.w;
            a30 += a.w*w.x; a31 += a.w*w.y; a32 += a.w*w.z; a33 += a.w*w.w;
        }
        buf ^= 1;
    }

    const float4 bb = *(const float4*)&bias[n0 + tx*4];
    float r0x=a00+bb.x, r0y=a01+bb.y, r0z=a02+bb.z, r0w=a03+bb.w;
    float r1x=a10+bb.x, r1y=a11+bb.y, r1z=a12+bb.z, r1w=a13+bb.w;
    float r2x=a20+bb.x, r2y=a21+bb.y, r2z=a22+bb.z, r2w=a23+bb.w;
    float r3x=a30+bb.x, r3y=a31+bb.y, r3z=a32+bb.z, r3w=a33+bb.w;

    if (H) {
        __half* Hp = H + (size_t)(m0 + ty*4) * N + n0 + tx*4;
        __half2 p0, p1;
        p0 = __floats2half2_rn(r0x, r0y); p1 = __floats2half2_rn(r0z, r0w);
        *(uint2*)(Hp)       = make_uint2(*(unsigned int*)&p0, *(unsigned int*)&p1);
        p0 = __floats2half2_rn(r1x, r1y); p1 = __floats2half2_rn(r1z, r1w);
        *(uint2*)(Hp + N)   = make_uint2(*(unsigned int*)&p0, *(unsigned int*)&p1);
        p0 = __floats2half2_rn(r2x, r2y); p1 = __floats2half2_rn(r2z, r2w);
        *(uint2*)(Hp + 2*N) = make_uint2(*(unsigned int*)&p0, *(unsigned int*)&p1);
        p0 = __floats2half2_rn(r3x, r3y); p1 = __floats2half2_rn(r3z, r3w);
        *(uint2*)(Hp + 3*N) = make_uint2(*(unsigned int*)&p0, *(unsigned int*)&p1);
    } else {
        float* Cp = C + (size_t)(m0 + ty*4) * N + n0 + tx*4;
        float4 o;
        o.x=r0x; o.y=r0y; o.z=r0z; o.w=r0w; *(float4*)(Cp)       = o;
        o.x=r1x; o.y=r1y; o.z=r1z; o.w=r1w; *(float4*)(Cp + N)   = o;
        o.x=r2x; o.y=r2y; o.z=r2z; o.w=r2w; *(float4*)(Cp + 2*N) = o;
        o.x=r3x; o.y=r3y; o.z=r3z; o.w=r3w; *(float4*)(Cp + 3*N) = o;
    }
}

// Phase-shift no-op: makes launches-per-call = 4 so ncu (-s 5 -c 1) lands on
// attn_kernel (launch #6 = call 2, position 2).
__global__ void noop_kernel() {}

// ---------------------------------------------------------------------------
// Fused additive-attention kernel, v7:
//  * score: CK=64 chunks (8), single 8KB half-K buffer, register-prefetch
//    LDG(uint4)->STS, XOR-swizzled rows, 8 accumulators (v5 structure).
//  * AV: 3-buffer cp.async.ca (L1-caching), 16-row chunks.
// Smem: scT 40960B + union 12288B + qh 2048B + vh 128B = 55424B -> 4 blocks/SM.
// ---------------------------------------------------------------------------
#define SCT_PITCH 20
#define CKK 64
#define NCHK (SKL/CKK)    /* 8  */
#define CKV 16
#define NCHV (SKL/CKV)    /* 32 */
#define UNION_FLOATS 3072
#define ATTN_SMEM_FLOATS (SKL*SCT_PITCH + UNION_FLOATS + 512 + 32)

__global__ __launch_bounds__(256, 4) void attn_kernel(
    const float* __restrict__ vparam, float* __restrict__ attn_out)
{
    extern __shared__ float smem[];
    float*  scT = smem;                           // [512][20]
    float*  uni = scT + SKL*SCT_PITCH;            // union staging
    __half* qh  = (__half*)(uni + UNION_FLOATS);  // [16][64]
    __half* vh  = qh + 16*64;                     // [64]

    const int tid  = threadIdx.x;
    const int lane = tid & 31;
    const int warp = tid >> 5;
    const int b  = blockIdx.z;
    const int h  = blockIdx.y;
    const int q0t = blockIdx.x << 4;

    if (tid < 64) vh[tid] = __float2half(vparam[h*HDIM + tid]);
    {
        int row = tid >> 4;
        int seg = tid & 15;
        const uint2* src = (const uint2*)&g_Qh[((size_t)(b*SQL + q0t + row))*EMBED + h*HDIM + seg*4];
        *(uint2*)&qh[row*64 + seg*4] = *src;
    }

    const float scale = 0.125f;
    const int qa = warp*2;
    const int qb = qa + 1;

    // ============ score phase: 8 chunks of 64 k-rows, reg-prefetch ==========
    {
        __half* kb = (__half*)uni;            // [64 rows][64 halves] swizzled
        const int krow = tid >> 2;            // 0..63
        const int kq   = tid & 3;             // 2 x 16B segs per thread
        const int s0 = kq*2, s1 = kq*2 + 1;
        const int sw0 = s0 ^ (krow & 7), sw1 = s1 ^ (krow & 7);
        const __half* Kg = &g_Kh[((size_t)(b*SKL))*EMBED + h*HDIM];

        uint4 kpre0 = *(const uint4*)(Kg + (size_t)krow*EMBED + s0*8);
        uint4 kpre1 = *(const uint4*)(Kg + (size_t)krow*EMBED + s1*8);
        *(uint4*)&kb[krow*64 + sw0*8] = kpre0;
        *(uint4*)&kb[krow*64 + sw1*8] = kpre1;
        __syncthreads();

        for (int c = 0; c < NCHK; c++) {
            if (c + 1 < NCHK) {
                kpre0 = *(const uint4*)(Kg + (size_t)((c+1)*CKK + krow)*EMBED + s0*8);
                kpre1 = *(const uint4*)(Kg + (size_t)((c+1)*CKK + krow)*EMBED + s1*8);
            }

            const uint4* qa4p = (const uint4*)&qh[qa*64];
            const uint4* qb4p = (const uint4*)&qh[qb*64];
            const uint4* vv4p = (const uint4*)vh;
            const __half* kr0 = kb + lane*64;
            const __half* kr1 = kb + (lane+32)*64;
            const int sw = lane & 7;

            __half2 z = __float2half2_rn(0.f);
            __half2 acc00a=z, acc00b=z, acc01a=z, acc01b=z;
            __half2 acc10a=z, acc10b=z, acc11a=z, acc11b=z;

            #pragma unroll
            for (int db = 0; db < 8; db++) {
                uint4 k04 = *(const uint4*)(kr0 + ((db ^ sw) * 8));
                uint4 k14 = *(const uint4*)(kr1 + ((db ^ sw) * 8));
                uint4 qa4 = qa4p[db];
                uint4 qb4 = qb4p[db];
                uint4 vv4 = vv4p[db];

                __half2 k00=u2h(k04.x), k01=u2h(k04.y), k02=u2h(k04.z), k03=u2h(k04.w);
                __half2 k10=u2h(k14.x), k11=u2h(k14.y), k12=u2h(k14.z), k13=u2h(k14.w);
                __half2 qa0=u2h(qa4.x), qa1=u2h(qa4.y), qa2=u2h(qa4.z), qa3=u2h(qa4.w);
                __half2 qb0=u2h(qb4.x), qb1=u2h(qb4.y), qb2=u2h(qb4.z), qb3=u2h(qb4.w);
                __half2 v0=u2h(vv4.x), v1=u2h(vv4.y), v2=u2h(vv4.z), v3=u2h(vv4.w);

                acc00a = __hfma2(v0, htanh2(__hadd2(qa0, k00)), acc00a);
                acc01a = __hfma2(v0, htanh2(__hadd2(qa0, k10)), acc01a);
                acc10a = __hfma2(v0, htanh2(__hadd2(qb0, k00)), acc10a);
                acc11a = __hfma2(v0, htanh2(__hadd2(qb0, k10)), acc11a);

                acc00b = __hfma2(v1, htanh2(__hadd2(qa1, k01)), acc00b);
                acc01b = __hfma2(v1, htanh2(__hadd2(qa1, k11)), acc01b);
                acc10b = __hfma2(v1, htanh2(__hadd2(qb1, k01)), acc10b);
                acc11b = __hfma2(v1, htanh2(__hadd2(qb1, k11)), acc11b);

                acc00a = __hfma2(v2, htanh2(__hadd2(qa2, k02)), acc00a);
                acc01a = __hfma2(v2, htanh2(__hadd2(qa2, k12)), acc01a);
                acc10a = __hfma2(v2, htanh2(__hadd2(qb2, k02)), acc10a);
                acc11a = __hfma2(v2, htanh2(__hadd2(qb2, k12)), acc11a);

                acc00b = __hfma2(v3, htanh2(__hadd2(qa3, k03)), acc00b);
                acc01b = __hfma2(v3, htanh2(__hadd2(qa3, k13)), acc01b);
                acc10b = __hfma2(v3, htanh2(__hadd2(qb3, k03)), acc10b);
                acc11b = __hfma2(v3, htanh2(__hadd2(qb3, k13)), acc11b);
            }

            scT[(c*CKK + lane)      * SCT_PITCH + qa] = (sumh2(acc00a) + sumh2(acc00b)) * scale;
            scT[(c*CKK + lane + 32) * SCT_PITCH + qa] = (sumh2(acc01a) + sumh2(acc01b)) * scale;
            scT[(c*CKK + lane)      * SCT_PITCH + qb] = (sumh2(acc10a) + sumh2(acc10b)) * scale;
            scT[(c*CKK + lane + 32) * SCT_PITCH + qb] = (sumh2(acc11a) + sumh2(acc11b)) * scale;

            __syncthreads();
            if (c + 1 < NCHK) {
                *(uint4*)&kb[krow*64 + sw0*8] = kpre0;
                *(uint4*)&kb[krow*64 + sw1*8] = kpre1;
                __syncthreads();
            }
        }
    }
    __syncthreads();

    // ---- prime V chunks 0,1 (overlaps softmax) ----
    {
        const int vrow = tid >> 4;
        const int vseg = tid & 15;
        const float* Vg = &g_V[((size_t)(b*SKL))*EMBED + h*HDIM];
        cp_async16_ca(&uni[vrow*64 + vseg*4], Vg + ((size_t)(0*CKV + vrow))*EMBED + vseg*4);
        cp_commit();
        cp_async16_ca(&uni[1024 + vrow*64 + vseg*4], Vg + ((size_t)(1*CKV + vrow))*EMBED + vseg*4);
        cp_commit();
    }

    // ---------------- softmax (each warp: 2 rows of 512) ----------------
    #pragma unroll
    for (int qq = 0; qq < 2; qq++) {
        const int q = qa + qq;
        float x[16];
        #pragma unroll
        for (int j = 0; j < 16; j++) x[j] = scT[(lane + 32*j)*SCT_PITCH + q];
        float m = -1e30f;
        #pragma unroll
        for (int j = 0; j < 16; j++) m = fmaxf(m, x[j]);
        #pragma unroll
        for (int o = 16; o; o >>= 1) m = fmaxf(m, __shfl_xor_sync(0xffffffffu, m, o));
        float s = 0.f;
        #pragma unroll
        for (int j = 0; j < 16; j++) { x[j] = __expf(x[j] - m); s += x[j]; }
        #pragma unroll
        for (int o = 16; o; o >>= 1) s += __shfl_xor_sync(0xffffffffu, s, o);
        const float r = 1.0f / s;
        float* arow = attn_out + ((size_t)((b*HEADS + h)*SQL + q0t + q))*SKL;
        #pragma unroll
        for (int j = 0; j < 16; j++) {
            float p = x[j] * r;
            scT[(lane + 32*j)*SCT_PITCH + q] = p;
            arow[lane + 32*j] = p;
        }
    }

    // ================= AV phase: 32 chunks of 16 k-rows =================
    {
        float* vb[3] = { uni, uni + 1024, uni + 2048 };
        const int vrow = tid >> 4;
        const int vseg = tid & 15;
        const float* Vg = &g_V[((size_t)(b*SKL))*EMBED + h*HDIM];

        const int g  = lane >> 3;
        const int dl = warp*8 + (lane & 7);
        float a0=0.f, a1=0.f, a2=0.f, a3=0.f;

        for (int c = 0; c < NCHV; c++) {
            if (c + 1 < NCHV) cp_wait<1>(); else cp_wait<0>();
            __syncthreads();
            if (c + 2 < NCHV) {
                cp_async16_ca(&vb[(c+2)%3][vrow*64 + vseg*4],
                              Vg + ((size_t)((c+2)*CKV + vrow))*EMBED + vseg*4);
                cp_commit();
            }

            const float* pb = &scT[(c*CKV)*SCT_PITCH + 4*g];
            const float* vbp = vb[c%3] + dl;
            #pragma unroll
            for (int kp = 0; kp < CKV; kp++) {
                float4 p = *(const float4*)(pb + kp*SCT_PITCH);
                float  v = vbp[kp*64];
                a0 += p.x*v; a1 += p.y*v; a2 += p.z*v; a3 += p.w*v;
            }
        }

        float* abase = &g_att[((size_t)(b*SQL + q0t + 4*g))*EMBED + h*HDIM + dl];
        abase[0]       = a0;
        abase[EMBED]   = a1;
        abase[2*EMBED] = a2;
        abase[3*EMBED] = a3;
    }
}

// ---------------------------------------------------------------------------
extern "C" void kernel_launch(void* const* d_in, const int* in_sizes, int n_in,
                              void* d_out, int out_size)
{
    (void)in_sizes; (void)n_in; (void)out_size;
    const float* query = (const float*)d_in[0];
    const float* key_  = (const float*)d_in[1];
    const float* value = (const float*)d_in[2];
    const float* Wq = (const float*)d_in[3];
    const float* bq = (const float*)d_in[4];
    const float* Wk = (const float*)d_in[5];
    const float* bk = (const float*)d_in[6];
    const float* Wv = (const float*)d_in[7];
    const float* bv = (const float*)d_in[8];
    const float* vp = (const float*)d_in[9];
    const float* Wo = (const float*)d_in[10];
    const float* bo = (const float*)d_in[11];

    float* out  = (float*)d_out;                 // [B, SQ, EMBED]
    float* attn = out + (size_t)MTOT * EMBED;    // [B, H, SQ, SK]

    __half *gQh, *gKh;
    float *gV, *gA;
    cudaGetSymbolAddress((void**)&gQh, g_Qh);
    cudaGetSymbolAddress((void**)&gKh, g_Kh);
    cudaGetSymbolAddress((void**)&gV,  g_V);
    cudaGetSymbolAddress((void**)&gA,  g_att);

    const int smem_bytes = ATTN_SMEM_FLOATS * (int)sizeof(float);
    cudaFuncSetAttribute(attn_kernel, cudaFuncAttributeMaxDynamicSharedMemorySize, smem_bytes);

    dim3 ggrid3(EMBED/64, MTOT/64, 3);   // (4, 32, 3)
    gemm_bias3_kernel<<<ggrid3, 256>>>(query, key_, value,
                                       Wq, Wk, Wv,
                                       bq, bk, bv,
                                       nullptr, nullptr, gV,
                                       gQh, gKh, nullptr,
                                       MTOT, EMBED, EMBED);

    dim3 agrid(SQL/16, HEADS, BATCH);  // (32, 4, 4)
    attn_kernel<<<agrid, 256, smem_bytes>>>(vp, attn);

    dim3 ggrid(EMBED/64, MTOT/64, 1);
    gemm_bias3_kernel<<<ggrid, 256>>>(gA, gA, gA,
                                      Wo, Wo, Wo,
                                      bo, bo, bo,
                                      out, out, out,
                                      nullptr, nullptr, nullptr,
                                      MTOT, EMBED, EMBED);

    // phase-shift launch so ncu -s 5 -c 1 captures attn_kernel next run
    noop_kernel<<<1, 1>>>();
}

// round 11
// speedup vs baseline: 1.0612x; 1.0330x over previous
#include <cuda_runtime.h>
#include <cuda_fp16.h>
#include <cstdint>

#define EMBED 256
#define HEADS 4
#define HDIM  64
#define BATCH 4
#define SQL   512
#define SKL   512
#define MTOT  (BATCH*SQL)   /* 2048 */

// Scratch (allocation-free rule: __device__ globals)
__device__ __half g_Qh[MTOT*EMBED];   // Q projection, half
__device__ __half g_Kh[MTOT*EMBED];   // K projection, half
__device__ float  g_V [MTOT*EMBED];   // V projection, f32
__device__ float  g_att[MTOT*EMBED];  // attended, f32

__device__ __forceinline__ __half2 htanh2(__half2 x) {
    unsigned int xi = *reinterpret_cast<unsigned int*>(&x);
    unsigned int yi;
    asm("tanh.approx.f16x2 %0, %1;" : "=r"(yi) : "r"(xi));
    return *reinterpret_cast<__half2*>(&yi);
}
__device__ __forceinline__ float sumh2(__half2 h) {
    float2 f = __half22float2(h);
    return f.x + f.y;
}
__device__ __forceinline__ __half2 u2h(unsigned int u) {
    return *reinterpret_cast<__half2*>(&u);
}
__device__ __forceinline__ void cp_async16_ca(void* smem_dst, const void* gsrc) {
    unsigned int saddr = (unsigned int)__cvta_generic_to_shared(smem_dst);
    asm volatile("cp.async.ca.shared.global [%0], [%1], 16;\n" :: "r"(saddr), "l"(gsrc));
}
__device__ __forceinline__ void cp_commit() {
    asm volatile("cp.async.commit_group;\n");
}
template<int N>
__device__ __forceinline__ void cp_wait() {
    asm volatile("cp.async.wait_group %0;\n" :: "n"(N));
}

// ---------------------------------------------------------------------------
// C[M,N] = A[M,K] @ W[N,K]^T + bias[N]  (torch Linear). grid.z picks problem;
// Hz != nullptr -> write half to Hz, else f32 to Cz.
// ---------------------------------------------------------------------------
__global__ __launch_bounds__(256) void gemm_bias3_kernel(
    const float* __restrict__ A0, const float* __restrict__ A1, const float* __restrict__ A2,
    const float* __restrict__ W0, const float* __restrict__ W1, const float* __restrict__ W2,
    const float* __restrict__ b0, const float* __restrict__ b1, const float* __restrict__ b2,
    float* __restrict__ C0, float* __restrict__ C1, float* __restrict__ C2,
    __half* __restrict__ H0, __half* __restrict__ H1, __half* __restrict__ H2,
    int M, int N, int K)
{
    const float* A; const float* W; const float* bias; float* C; __half* H;
    if (blockIdx.z == 0)      { A = A0; W = W0; bias = b0; C = C0; H = H0; }
    else if (blockIdx.z == 1) { A = A1; W = W1; bias = b1; C = C1; H = H1; }
    else                      { A = A2; W = W2; bias = b2; C = C2; H = H2; }

    __shared__ float As[2][16][68];
    __shared__ float Ws[2][16][68];
    const int tid = threadIdx.x;
    const int tx  = tid & 15;
    const int ty  = tid >> 4;
    const int n0  = blockIdx.x * 64;
    const int m0  = blockIdx.y * 64;

    const int lr = tid >> 2;
    const int lc = (tid & 3) << 2;
    const float* Ag = A + (size_t)(m0 + lr) * K + lc;
    const float* Wg = W + (size_t)(n0 + lr) * K + lc;

    float a00=0,a01=0,a02=0,a03=0, a10=0,a11=0,a12=0,a13=0;
    float a20=0,a21=0,a22=0,a23=0, a30=0,a31=0,a32=0,a33=0;

    float4 av = *(const float4*)(Ag);
    float4 wv = *(const float4*)(Wg);
    int buf = 0;

    for (int k0 = 0; k0 < K; k0 += 16) {
        As[buf][lc+0][lr] = av.x; As[buf][lc+1][lr] = av.y;
        As[buf][lc+2][lr] = av.z; As[buf][lc+3][lr] = av.w;
        Ws[buf][lc+0][lr] = wv.x; Ws[buf][lc+1][lr] = wv.y;
        Ws[buf][lc+2][lr] = wv.z; Ws[buf][lc+3][lr] = wv.w;
        __syncthreads();
        if (k0 + 16 < K) {
            av = *(const float4*)(Ag + k0 + 16);
            wv = *(const float4*)(Wg + k0 + 16);
        }
        #pragma unroll
        for (int k = 0; k < 16; k++) {
            float4 a = *(const float4*)&As[buf][k][ty*4];
            float4 w = *(const float4*)&Ws[buf][k][tx*4];
            a00 += a.x*w.x; a01 += a.x*w.y; a02 += a.x*w.z; a03 += a.x*w.w;
            a10 += a.y*w.x; a11 += a.y*w.y; a12 += a.y*w.z; a13 += a.y*w.w;
            a20 += a.z*w.x; a21 += a.z*w.y; a22 += a.z*w.z; a23 += a.z*w.w;
            a30 += a.w*w.x; a31 += a.w*w.y; a32 += a.w*w.z; a33 += a.w*w.w;
        }
        buf ^= 1;
    }

    const float4 bb = *(const float4*)&bias[n0 + tx*4];
    float r0x=a00+bb.x, r0y=a01+bb.y, r0z=a02+bb.z, r0w=a03+bb.w;
    float r1x=a10+bb.x, r1y=a11+bb.y, r1z=a12+bb.z, r1w=a13+bb.w;
    float r2x=a20+bb.x, r2y=a21+bb.y, r2z=a22+bb.z, r2w=a23+bb.w;
    float r3x=a30+bb.x, r3y=a31+bb.y, r3z=a32+bb.z, r3w=a33+bb.w;

    if (H) {
        __half* Hp = H + (size_t)(m0 + ty*4) * N + n0 + tx*4;
        __half2 p0, p1;
        p0 = __floats2half2_rn(r0x, r0y); p1 = __floats2half2_rn(r0z, r0w);
        *(uint2*)(Hp)       = make_uint2(*(unsigned int*)&p0, *(unsigned int*)&p1);
        p0 = __floats2half2_rn(r1x, r1y); p1 = __floats2half2_rn(r1z, r1w);
        *(uint2*)(Hp + N)   = make_uint2(*(unsigned int*)&p0, *(unsigned int*)&p1);
        p0 = __floats2half2_rn(r2x, r2y); p1 = __floats2half2_rn(r2z, r2w);
        *(uint2*)(Hp + 2*N) = make_uint2(*(unsigned int*)&p0, *(unsigned int*)&p1);
        p0 = __floats2half2_rn(r3x, r3y); p1 = __floats2half2_rn(r3z, r3w);
        *(uint2*)(Hp + 3*N) = make_uint2(*(unsigned int*)&p0, *(unsigned int*)&p1);
    } else {
        float* Cp = C + (size_t)(m0 + ty*4) * N + n0 + tx*4;
        float4 o;
        o.x=r0x; o.y=r0y; o.z=r0z; o.w=r0w; *(float4*)(Cp)       = o;
        o.x=r1x; o.y=r1y; o.z=r1z; o.w=r1w; *(float4*)(Cp + N)   = o;
        o.x=r2x; o.y=r2y; o.z=r2z; o.w=r2w; *(float4*)(Cp + 2*N) = o;
        o.x=r3x; o.y=r3y; o.z=r3z; o.w=r3w; *(float4*)(Cp + 3*N) = o;
    }
}

// Profiling phase-shift no-op. Captured launch index satisfies idx ≡ 3 (mod 6)
// (consistent with all prior captures), so with 6 launches/call the kernel at
// position 3 is always profiled -> place attn there.
__global__ void noop_kernel() {}

// ---------------------------------------------------------------------------
// Fused additive-attention kernel, v8:
//  * score: CK=64 chunks (8), half-K from GEMM, reg-prefetch LDG(uint4)->STS,
//    XOR-swizzled rows (v7 structure).
//  * AV: v5 structure — CKV=32 f32 rows, reg-prefetch, 16 chunk-syncs;
//    chunk 0 primed by cp.async.ca overlapping softmax.
// Smem floats: scT 10240 + union 2176 + qh 512 + vh 32 = 12960 (51840B)
//  -> 4 blocks/SM, single wave for grid 512.
// ---------------------------------------------------------------------------
#define SCT_PITCH 20
#define CKK 64
#define NCHK (SKL/CKK)    /* 8  */
#define CKV 32
#define NCHV (SKL/CKV)    /* 16 */
#define VF_PITCH 68
#define UNION_FLOATS 2176
#define ATTN_SMEM_FLOATS (SKL*SCT_PITCH + UNION_FLOATS + 512 + 32)

__global__ __launch_bounds__(256, 4) void attn_kernel(
    const float* __restrict__ vparam, float* __restrict__ attn_out)
{
    extern __shared__ float smem[];
    float*  scT = smem;                           // [512][20]
    float*  uni = scT + SKL*SCT_PITCH;            // union staging
    __half* qh  = (__half*)(uni + UNION_FLOATS);  // [16][64]
    __half* vh  = qh + 16*64;                     // [64]

    const int tid  = threadIdx.x;
    const int lane = tid & 31;
    const int warp = tid >> 5;
    const int b  = blockIdx.z;
    const int h  = blockIdx.y;
    const int q0t = blockIdx.x << 4;

    if (tid < 64) vh[tid] = __float2half(vparam[h*HDIM + tid]);
    {
        int row = tid >> 4;
        int seg = tid & 15;
        const uint2* src = (const uint2*)&g_Qh[((size_t)(b*SQL + q0t + row))*EMBED + h*HDIM + seg*4];
        *(uint2*)&qh[row*64 + seg*4] = *src;
    }

    const float scale = 0.125f;
    const int qa = warp*2;
    const int qb = qa + 1;

    // ============ score phase: 8 chunks of 64 k-rows, reg-prefetch ==========
    {
        __half* kb = (__half*)uni;            // [64 rows][64 halves] swizzled
        const int krow = tid >> 2;            // 0..63
        const int kq   = tid & 3;             // 2 x 16B segs per thread
        const int s0 = kq*2, s1 = kq*2 + 1;
        const int sw0 = s0 ^ (krow & 7), sw1 = s1 ^ (krow & 7);
        const __half* Kg = &g_Kh[((size_t)(b*SKL))*EMBED + h*HDIM];

        uint4 kpre0 = *(const uint4*)(Kg + (size_t)krow*EMBED + s0*8);
        uint4 kpre1 = *(const uint4*)(Kg + (size_t)krow*EMBED + s1*8);
        *(uint4*)&kb[krow*64 + sw0*8] = kpre0;
        *(uint4*)&kb[krow*64 + sw1*8] = kpre1;
        __syncthreads();

        for (int c = 0; c < NCHK; c++) {
            if (c + 1 < NCHK) {
                kpre0 = *(const uint4*)(Kg + (size_t)((c+1)*CKK + krow)*EMBED + s0*8);
                kpre1 = *(const uint4*)(Kg + (size_t)((c+1)*CKK + krow)*EMBED + s1*8);
            }

            const uint4* qa4p = (const uint4*)&qh[qa*64];
            const uint4* qb4p = (const uint4*)&qh[qb*64];
            const uint4* vv4p = (const uint4*)vh;
            const __half* kr0 = kb + lane*64;
            const __half* kr1 = kb + (lane+32)*64;
            const int sw = lane & 7;

            __half2 z = __float2half2_rn(0.f);
            __half2 acc00a=z, acc00b=z, acc01a=z, acc01b=z;
            __half2 acc10a=z, acc10b=z, acc11a=z, acc11b=z;

            #pragma unroll
            for (int db = 0; db < 8; db++) {
                uint4 k04 = *(const uint4*)(kr0 + ((db ^ sw) * 8));
                uint4 k14 = *(const uint4*)(kr1 + ((db ^ sw) * 8));
                uint4 qa4 = qa4p[db];
                uint4 qb4 = qb4p[db];
                uint4 vv4 = vv4p[db];

                __half2 k00=u2h(k04.x), k01=u2h(k04.y), k02=u2h(k04.z), k03=u2h(k04.w);
                __half2 k10=u2h(k14.x), k11=u2h(k14.y), k12=u2h(k14.z), k13=u2h(k14.w);
                __half2 qa0=u2h(qa4.x), qa1=u2h(qa4.y), qa2=u2h(qa4.z), qa3=u2h(qa4.w);
                __half2 qb0=u2h(qb4.x), qb1=u2h(qb4.y), qb2=u2h(qb4.z), qb3=u2h(qb4.w);
                __half2 v0=u2h(vv4.x), v1=u2h(vv4.y), v2=u2h(vv4.z), v3=u2h(vv4.w);

                acc00a = __hfma2(v0, htanh2(__hadd2(qa0, k00)), acc00a);
                acc01a = __hfma2(v0, htanh2(__hadd2(qa0, k10)), acc01a);
                acc10a = __hfma2(v0, htanh2(__hadd2(qb0, k00)), acc10a);
                acc11a = __hfma2(v0, htanh2(__hadd2(qb0, k10)), acc11a);

                acc00b = __hfma2(v1, htanh2(__hadd2(qa1, k01)), acc00b);
                acc01b = __hfma2(v1, htanh2(__hadd2(qa1, k11)), acc01b);
                acc10b = __hfma2(v1, htanh2(__hadd2(qb1, k01)), acc10b);
                acc11b = __hfma2(v1, htanh2(__hadd2(qb1, k11)), acc11b);

                acc00a = __hfma2(v2, htanh2(__hadd2(qa2, k02)), acc00a);
                acc01a = __hfma2(v2, htanh2(__hadd2(qa2, k12)), acc01a);
                acc10a = __hfma2(v2, htanh2(__hadd2(qb2, k02)), acc10a);
                acc11a = __hfma2(v2, htanh2(__hadd2(qb2, k12)), acc11a);

                acc00b = __hfma2(v3, htanh2(__hadd2(qa3, k03)), acc00b);
                acc01b = __hfma2(v3, htanh2(__hadd2(qa3, k13)), acc01b);
                acc10b = __hfma2(v3, htanh2(__hadd2(qb3, k03)), acc10b);
                acc11b = __hfma2(v3, htanh2(__hadd2(qb3, k13)), acc11b);
            }

            scT[(c*CKK + lane)      * SCT_PITCH + qa] = (sumh2(acc00a) + sumh2(acc00b)) * scale;
            scT[(c*CKK + lane + 32) * SCT_PITCH + qa] = (sumh2(acc01a) + sumh2(acc01b)) * scale;
            scT[(c*CKK + lane)      * SCT_PITCH + qb] = (sumh2(acc10a) + sumh2(acc10b)) * scale;
            scT[(c*CKK + lane + 32) * SCT_PITCH + qb] = (sumh2(acc11a) + sumh2(acc11b)) * scale;

            __syncthreads();
            if (c + 1 < NCHK) {
                *(uint4*)&kb[krow*64 + sw0*8] = kpre0;
                *(uint4*)&kb[krow*64 + sw1*8] = kpre1;
                __syncthreads();
            }
        }
    }
    __syncthreads();

    // ---- prime V chunk 0 (32 rows) via cp.async, overlapping softmax ----
    {
        const int vrow  = tid >> 4;          // 0..15
        const int vseg4 = (tid & 15) << 2;   // 0,4,..,60
        const float* Vg = &g_V[((size_t)(b*SKL))*EMBED + h*HDIM];
        cp_async16_ca(&uni[vrow*VF_PITCH + vseg4],      Vg + (size_t)vrow*EMBED + vseg4);
        cp_async16_ca(&uni[(vrow+16)*VF_PITCH + vseg4], Vg + (size_t)(vrow+16)*EMBED + vseg4);
        cp_commit();
    }

    // ---------------- softmax (each warp: 2 rows of 512) ----------------
    #pragma unroll
    for (int qq = 0; qq < 2; qq++) {
        const int q = qa + qq;
        float x[16];
        #pragma unroll
        for (int j = 0; j < 16; j++) x[j] = scT[(lane + 32*j)*SCT_PITCH + q];
        float m = -1e30f;
        #pragma unroll
        for (int j = 0; j < 16; j++) m = fmaxf(m, x[j]);
        #pragma unroll
        for (int o = 16; o; o >>= 1) m = fmaxf(m, __shfl_xor_sync(0xffffffffu, m, o));
        float s = 0.f;
        #pragma unroll
        for (int j = 0; j < 16; j++) { x[j] = __expf(x[j] - m); s += x[j]; }
        #pragma unroll
        for (int o = 16; o; o >>= 1) s += __shfl_xor_sync(0xffffffffu, s, o);
        const float r = 1.0f / s;
        float* arow = attn_out + ((size_t)((b*HEADS + h)*SQL + q0t + q))*SKL;
        #pragma unroll
        for (int j = 0; j < 16; j++) {
            float p = x[j] * r;
            scT[(lane + 32*j)*SCT_PITCH + q] = p;
            arow[lane + 32*j] = p;
        }
    }

    // ========= AV phase: 16 chunks of 32 k-rows, reg-prefetch (v5) =========
    {
        float* kvf = uni;                    // [32][68]
        const int vrow  = tid >> 4;
        const int vseg4 = (tid & 15) << 2;
        const float* Vg = &g_V[((size_t)(b*SKL))*EMBED + h*HDIM];
        const int g  = lane >> 3;            // q-group: q = 4g..4g+3
        const int dl = warp*8 + (lane & 7);  // this thread's d

        cp_wait<0>();
        __syncthreads();                     // chunk 0 resident

        float4 vpre[2];
        float a0=0.f, a1=0.f, a2=0.f, a3=0.f;
        for (int c = 0; c < NCHV; c++) {
            if (c + 1 < NCHV) {
                #pragma unroll
                for (int it = 0; it < 2; it++)
                    vpre[it] = *(const float4*)(Vg + ((size_t)((c+1)*CKV + vrow + it*16))*EMBED + vseg4);
            }
            const float* pb  = &scT[(c*CKV)*SCT_PITCH + 4*g];
            const float* vbp = kvf + dl;
            #pragma unroll 8
            for (int kp = 0; kp < CKV; kp++) {
                float4 p = *(const float4*)(pb + kp*SCT_PITCH);
                float  v = vbp[kp*VF_PITCH];
                a0 += p.x*v; a1 += p.y*v; a2 += p.z*v; a3 += p.w*v;
            }
            __syncthreads();
            if (c + 1 < NCHV) {
                #pragma unroll
                for (int it = 0; it < 2; it++)
                    *(float4*)&kvf[(vrow + it*16)*VF_PITCH + vseg4] = vpre[it];
                __syncthreads();
            }
        }

        float* abase = &g_att[((size_t)(b*SQL + q0t + 4*g))*EMBED + h*HDIM + dl];
        abase[0]       = a0;
        abase[EMBED]   = a1;
        abase[2*EMBED] = a2;
        abase[3*EMBED] = a3;
    }
}

// ---------------------------------------------------------------------------
extern "C" void kernel_launch(void* const* d_in, const int* in_sizes, int n_in,
                              void* d_out, int out_size)
{
    (void)in_sizes; (void)n_in; (void)out_size;
    const float* query = (const float*)d_in[0];
    const float* key_  = (const float*)d_in[1];
    const float* value = (const float*)d_in[2];
    const float* Wq = (const float*)d_in[3];
    const float* bq = (const float*)d_in[4];
    const float* Wk = (const float*)d_in[5];
    const float* bk = (const float*)d_in[6];
    const float* Wv = (const float*)d_in[7];
    const float* bv = (const float*)d_in[8];
    const float* vp = (const float*)d_in[9];
    const float* Wo = (const float*)d_in[10];
    const float* bo = (const float*)d_in[11];

    float* out  = (float*)d_out;                 // [B, SQ, EMBED]
    float* attn = out + (size_t)MTOT * EMBED;    // [B, H, SQ, SK]

    __half *gQh, *gKh;
    float *gV, *gA;
    cudaGetSymbolAddress((void**)&gQh, g_Qh);
    cudaGetSymbolAddress((void**)&gKh, g_Kh);
    cudaGetSymbolAddress((void**)&gV,  g_V);
    cudaGetSymbolAddress((void**)&gA,  g_att);

    const int smem_bytes = ATTN_SMEM_FLOATS * (int)sizeof(float);
    cudaFuncSetAttribute(attn_kernel, cudaFuncAttributeMaxDynamicSharedMemorySize, smem_bytes);

    // Launch positions (6/call): 0 gemm3, 1 noop, 2 noop, 3 attn, 4 gemmO, 5 noop
    dim3 ggrid3(EMBED/64, MTOT/64, 3);
    gemm_bias3_kernel<<<ggrid3, 256>>>(query, key_, value,
                                       Wq, Wk, Wv,
                                       bq, bk, bv,
                                       nullptr, nullptr, gV,
                                       gQh, gKh, nullptr,
                                       MTOT, EMBED, EMBED);
    noop_kernel<<<1, 1>>>();
    noop_kernel<<<1, 1>>>();

    dim3 agrid(SQL/16, HEADS, BATCH);  // (32, 4, 4)
    attn_kernel<<<agrid, 256, smem_bytes>>>(vp, attn);

    dim3 ggrid(EMBED/64, MTOT/64, 1);
    gemm_bias3_kernel<<<ggrid, 256>>>(gA, gA, gA,
                                      Wo, Wo, Wo,
                                      bo, bo, bo,
                                      out, out, out,
                                      nullptr, nullptr, nullptr,
                                      MTOT, EMBED, EMBED);
    noop_kernel<<<1, 1>>>();
}

// round 12
// speedup vs baseline: 1.1315x; 1.0662x over previous
#include <cuda_runtime.h>
#include <cuda_fp16.h>
#include <cstdint>

#define EMBED 256
#define HEADS 4
#define HDIM  64
#define BATCH 4
#define SQL   512
#define SKL   512
#define MTOT  (BATCH*SQL)   /* 2048 */

// Scratch (allocation-free rule: __device__ globals)
__device__ __half g_Qh[MTOT*EMBED];   // Q projection, half
__device__ __half g_Kh[MTOT*EMBED];   // K projection, half
__device__ float  g_V [MTOT*EMBED];   // V projection, f32
__device__ float  g_att[MTOT*EMBED];  // attended, f32

__device__ __forceinline__ __half2 htanh2(__half2 x) {
    unsigned int xi = *reinterpret_cast<unsigned int*>(&x);
    unsigned int yi;
    asm("tanh.approx.f16x2 %0, %1;" : "=r"(yi) : "r"(xi));
    return *reinterpret_cast<__half2*>(&yi);
}

// FMA-pipe tanh: odd minimax-ish interpolant on |x|<=2.75 (clamped).
// t = xc * P(xc^2), P = c0 + c1 u + ... + c5 u^5 (Horner).
// Verified fit err <= ~2e-3 in-range, <= ~1e-2 in saturated tail.
__device__ __forceinline__ __half2 poly_tanh2(__half2 x) {
    const __half2 lo = __float2half2_rn(-2.75f);
    const __half2 hi = __float2half2_rn( 2.75f);
    __half2 xc = __hmax2(lo, __hmin2(x, hi));
    __half2 u  = __hmul2(xc, xc);
    __half2 p  = __hfma2(u, __float2half2_rn(-6.3914e-05f), __float2half2_rn(1.60803e-03f));
    p = __hfma2(u, p, __float2half2_rn(-1.63146e-02f));
    p = __hfma2(u, p, __float2half2_rn( 8.88551e-02f));
    p = __hfma2(u, p, __float2half2_rn(-3.096166e-01f));
    p = __hfma2(u, p, __float2half2_rn( 9.975679e-01f));
    return __hmul2(xc, p);
}

// Mixed tanh: compile-time selection (db is a constant in the unrolled loop),
// splitting tanh work across the MUFU and FMA pipes.
__device__ __forceinline__ __half2 tanh_mixed(__half2 x, bool use_poly) {
    return use_poly ? poly_tanh2(x) : htanh2(x);
}

__device__ __forceinline__ float sumh2(__half2 h) {
    float2 f = __half22float2(h);
    return f.x + f.y;
}
__device__ __forceinline__ __half2 u2h(unsigned int u) {
    return *reinterpret_cast<__half2*>(&u);
}
__device__ __forceinline__ void cp_async16_ca(void* smem_dst, const void* gsrc) {
    unsigned int saddr = (unsigned int)__cvta_generic_to_shared(smem_dst);
    asm volatile("cp.async.ca.shared.global [%0], [%1], 16;\n" :: "r"(saddr), "l"(gsrc));
}
__device__ __forceinline__ void cp_commit() {
    asm volatile("cp.async.commit_group;\n");
}
template<int N>
__device__ __forceinline__ void cp_wait() {
    asm volatile("cp.async.wait_group %0;\n" :: "n"(N));
}

// ---------------------------------------------------------------------------
// C[M,N] = A[M,K] @ W[N,K]^T + bias[N]  (torch Linear). grid.z picks problem;
// Hz != nullptr -> write half to Hz, else f32 to Cz.
// ---------------------------------------------------------------------------
__global__ __launch_bounds__(256) void gemm_bias3_kernel(
    const float* __restrict__ A0, const float* __restrict__ A1, const float* __restrict__ A2,
    const float* __restrict__ W0, const float* __restrict__ W1, const float* __restrict__ W2,
    const float* __restrict__ b0, const float* __restrict__ b1, const float* __restrict__ b2,
    float* __restrict__ C0, float* __restrict__ C1, float* __restrict__ C2,
    __half* __restrict__ H0, __half* __restrict__ H1, __half* __restrict__ H2,
    int M, int N, int K)
{
    const float* A; const float* W; const float* bias; float* C; __half* H;
    if (blockIdx.z == 0)      { A = A0; W = W0; bias = b0; C = C0; H = H0; }
    else if (blockIdx.z == 1) { A = A1; W = W1; bias = b1; C = C1; H = H1; }
    else                      { A = A2; W = W2; bias = b2; C = C2; H = H2; }

    __shared__ float As[2][16][68];
    __shared__ float Ws[2][16][68];
    const int tid = threadIdx.x;
    const int tx  = tid & 15;
    const int ty  = tid >> 4;
    const int n0  = blockIdx.x * 64;
    const int m0  = blockIdx.y * 64;

    const int lr = tid >> 2;
    const int lc = (tid & 3) << 2;
    const float* Ag = A + (size_t)(m0 + lr) * K + lc;
    const float* Wg = W + (size_t)(n0 + lr) * K + lc;

    float a00=0,a01=0,a02=0,a03=0, a10=0,a11=0,a12=0,a13=0;
    float a20=0,a21=0,a22=0,a23=0, a30=0,a31=0,a32=0,a33=0;

    float4 av = *(const float4*)(Ag);
    float4 wv = *(const float4*)(Wg);
    int buf = 0;

    for (int k0 = 0; k0 < K; k0 += 16) {
        As[buf][lc+0][lr] = av.x; As[buf][lc+1][lr] = av.y;
        As[buf][lc+2][lr] = av.z; As[buf][lc+3][lr] = av.w;
        Ws[buf][lc+0][lr] = wv.x; Ws[buf][lc+1][lr] = wv.y;
        Ws[buf][lc+2][lr] = wv.z; Ws[buf][lc+3][lr] = wv.w;
        __syncthreads();
        if (k0 + 16 < K) {
            av = *(const float4*)(Ag + k0 + 16);
            wv = *(const float4*)(Wg + k0 + 16);
        }
        #pragma unroll
        for (int k = 0; k < 16; k++) {
            float4 a = *(const float4*)&As[buf][k][ty*4];
            float4 w = *(const float4*)&Ws[buf][k][tx*4];
            a00 += a.x*w.x; a01 += a.x*w.y; a02 += a.x*w.z; a03 += a.x*w.w;
            a10 += a.y*w.x; a11 += a.y*w.y; a12 += a.y*w.z; a13 += a.y*w.w;
            a20 += a.z*w.x; a21 += a.z*w.y; a22 += a.z*w.z; a23 += a.z*w.w;
            a30 += a.w*w.x; a31 += a.w*w.y; a32 += a.w*w.z; a33 += a.w*w.w;
        }
        buf ^= 1;
    }

    const float4 bb = *(const float4*)&bias[n0 + tx*4];
    float r0x=a00+bb.x, r0y=a01+bb.y, r0z=a02+bb.z, r0w=a03+bb.w;
    float r1x=a10+bb.x, r1y=a11+bb.y, r1z=a12+bb.z, r1w=a13+bb.w;
    float r2x=a20+bb.x, r2y=a21+bb.y, r2z=a22+bb.z, r2w=a23+bb.w;
    float r3x=a30+bb.x, r3y=a31+bb.y, r3z=a32+bb.z, r3w=a33+bb.w;

    if (H) {
        __half* Hp = H + (size_t)(m0 + ty*4) * N + n0 + tx*4;
        __half2 p0, p1;
        p0 = __floats2half2_rn(r0x, r0y); p1 = __floats2half2_rn(r0z, r0w);
        *(uint2*)(Hp)       = make_uint2(*(unsigned int*)&p0, *(unsigned int*)&p1);
        p0 = __floats2half2_rn(r1x, r1y); p1 = __floats2half2_rn(r1z, r1w);
        *(uint2*)(Hp + N)   = make_uint2(*(unsigned int*)&p0, *(unsigned int*)&p1);
        p0 = __floats2half2_rn(r2x, r2y); p1 = __floats2half2_rn(r2z, r2w);
        *(uint2*)(Hp + 2*N) = make_uint2(*(unsigned int*)&p0, *(unsigned int*)&p1);
        p0 = __floats2half2_rn(r3x, r3y); p1 = __floats2half2_rn(r3z, r3w);
        *(uint2*)(Hp + 3*N) = make_uint2(*(unsigned int*)&p0, *(unsigned int*)&p1);
    } else {
        float* Cp = C + (size_t)(m0 + ty*4) * N + n0 + tx*4;
        float4 o;
        o.x=r0x; o.y=r0y; o.z=r0z; o.w=r0w; *(float4*)(Cp)       = o;
        o.x=r1x; o.y=r1y; o.z=r1z; o.w=r1w; *(float4*)(Cp + N)   = o;
        o.x=r2x; o.y=r2y; o.z=r2z; o.w=r2w; *(float4*)(Cp + 2*N) = o;
        o.x=r3x; o.y=r3y; o.z=r3z; o.w=r3w; *(float4*)(Cp + 3*N) = o;
    }
}

// ---------------------------------------------------------------------------
// Fused additive-attention kernel, v9 = v8 + MUFU/FMA hybrid tanh:
// d-blocks {1,4,6} of 8 use the FMA-pipe polynomial (f=0.375), the rest MUFU.
// Balances MUFU ~10cyc vs FMA ~9.3cyc per tanh-instr-equivalent (was 16 vs 4).
// ---------------------------------------------------------------------------
#define SCT_PITCH 20
#define CKK 64
#define NCHK (SKL/CKK)    /* 8  */
#define CKV 32
#define NCHV (SKL/CKV)    /* 16 */
#define VF_PITCH 68
#define UNION_FLOATS 2176
#define ATTN_SMEM_FLOATS (SKL*SCT_PITCH + UNION_FLOATS + 512 + 32)

__global__ __launch_bounds__(256, 4) void attn_kernel(
    const float* __restrict__ vparam, float* __restrict__ attn_out)
{
    extern __shared__ float smem[];
    float*  scT = smem;                           // [512][20]
    float*  uni = scT + SKL*SCT_PITCH;            // union staging
    __half* qh  = (__half*)(uni + UNION_FLOATS);  // [16][64]
    __half* vh  = qh + 16*64;                     // [64]

    const int tid  = threadIdx.x;
    const int lane = tid & 31;
    const int warp = tid >> 5;
    const int b  = blockIdx.z;
    const int h  = blockIdx.y;
    const int q0t = blockIdx.x << 4;

    if (tid < 64) vh[tid] = __float2half(vparam[h*HDIM + tid]);
    {
        int row = tid >> 4;
        int seg = tid & 15;
        const uint2* src = (const uint2*)&g_Qh[((size_t)(b*SQL + q0t + row))*EMBED + h*HDIM + seg*4];
        *(uint2*)&qh[row*64 + seg*4] = *src;
    }

    const float scale = 0.125f;
    const int qa = warp*2;
    const int qb = qa + 1;

    // ============ score phase: 8 chunks of 64 k-rows, reg-prefetch ==========
    {
        __half* kb = (__half*)uni;            // [64 rows][64 halves] swizzled
        const int krow = tid >> 2;            // 0..63
        const int kq   = tid & 3;             // 2 x 16B segs per thread
        const int s0 = kq*2, s1 = kq*2 + 1;
        const int sw0 = s0 ^ (krow & 7), sw1 = s1 ^ (krow & 7);
        const __half* Kg = &g_Kh[((size_t)(b*SKL))*EMBED + h*HDIM];

        uint4 kpre0 = *(const uint4*)(Kg + (size_t)krow*EMBED + s0*8);
        uint4 kpre1 = *(const uint4*)(Kg + (size_t)krow*EMBED + s1*8);
        *(uint4*)&kb[krow*64 + sw0*8] = kpre0;
        *(uint4*)&kb[krow*64 + sw1*8] = kpre1;
        __syncthreads();

        for (int c = 0; c < NCHK; c++) {
            if (c + 1 < NCHK) {
                kpre0 = *(const uint4*)(Kg + (size_t)((c+1)*CKK + krow)*EMBED + s0*8);
                kpre1 = *(const uint4*)(Kg + (size_t)((c+1)*CKK + krow)*EMBED + s1*8);
            }

            const uint4* qa4p = (const uint4*)&qh[qa*64];
            const uint4* qb4p = (const uint4*)&qh[qb*64];
            const uint4* vv4p = (const uint4*)vh;
            const __half* kr0 = kb + lane*64;
            const __half* kr1 = kb + (lane+32)*64;
            const int sw = lane & 7;

            __half2 z = __float2half2_rn(0.f);
            __half2 acc00a=z, acc00b=z, acc01a=z, acc01b=z;
            __half2 acc10a=z, acc10b=z, acc11a=z, acc11b=z;

            #pragma unroll
            for (int db = 0; db < 8; db++) {
                const bool up = (db == 1) || (db == 4) || (db == 6);  // f=3/8 poly
                uint4 k04 = *(const uint4*)(kr0 + ((db ^ sw) * 8));
                uint4 k14 = *(const uint4*)(kr1 + ((db ^ sw) * 8));
                uint4 qa4 = qa4p[db];
                uint4 qb4 = qb4p[db];
                uint4 vv4 = vv4p[db];

                __half2 k00=u2h(k04.x), k01=u2h(k04.y), k02=u2h(k04.z), k03=u2h(k04.w);
                __half2 k10=u2h(k14.x), k11=u2h(k14.y), k12=u2h(k14.z), k13=u2h(k14.w);
                __half2 qa0=u2h(qa4.x), qa1=u2h(qa4.y), qa2=u2h(qa4.z), qa3=u2h(qa4.w);
                __half2 qb0=u2h(qb4.x), qb1=u2h(qb4.y), qb2=u2h(qb4.z), qb3=u2h(qb4.w);
                __half2 v0=u2h(vv4.x), v1=u2h(vv4.y), v2=u2h(vv4.z), v3=u2h(vv4.w);

                acc00a = __hfma2(v0, tanh_mixed(__hadd2(qa0, k00), up), acc00a);
                acc01a = __hfma2(v0, tanh_mixed(__hadd2(qa0, k10), up), acc01a);
                acc10a = __hfma2(v0, tanh_mixed(__hadd2(qb0, k00), up), acc10a);
                acc11a = __hfma2(v0, tanh_mixed(__hadd2(qb0, k10), up), acc11a);

                acc00b = __hfma2(v1, tanh_mixed(__hadd2(qa1, k01), up), acc00b);
                acc01b = __hfma2(v1, tanh_mixed(__hadd2(qa1, k11), up), acc01b);
                acc10b = __hfma2(v1, tanh_mixed(__hadd2(qb1, k01), up), acc10b);
                acc11b = __hfma2(v1, tanh_mixed(__hadd2(qb1, k11), up), acc11b);

                acc00a = __hfma2(v2, tanh_mixed(__hadd2(qa2, k02), up), acc00a);
                acc01a = __hfma2(v2, tanh_mixed(__hadd2(qa2, k12), up), acc01a);
                acc10a = __hfma2(v2, tanh_mixed(__hadd2(qb2, k02), up), acc10a);
                acc11a = __hfma2(v2, tanh_mixed(__hadd2(qb2, k12), up), acc11a);

                acc00b = __hfma2(v3, tanh_mixed(__hadd2(qa3, k03), up), acc00b);
                acc01b = __hfma2(v3, tanh_mixed(__hadd2(qa3, k13), up), acc01b);
                acc10b = __hfma2(v3, tanh_mixed(__hadd2(qb3, k03), up), acc10b);
                acc11b = __hfma2(v3, tanh_mixed(__hadd2(qb3, k13), up), acc11b);
            }

            scT[(c*CKK + lane)      * SCT_PITCH + qa] = (sumh2(acc00a) + sumh2(acc00b)) * scale;
            scT[(c*CKK + lane + 32) * SCT_PITCH + qa] = (sumh2(acc01a) + sumh2(acc01b)) * scale;
            scT[(c*CKK + lane)      * SCT_PITCH + qb] = (sumh2(acc10a) + sumh2(acc10b)) * scale;
            scT[(c*CKK + lane + 32) * SCT_PITCH + qb] = (sumh2(acc11a) + sumh2(acc11b)) * scale;

            __syncthreads();
            if (c + 1 < NCHK) {
                *(uint4*)&kb[krow*64 + sw0*8] = kpre0;
                *(uint4*)&kb[krow*64 + sw1*8] = kpre1;
                __syncthreads();
            }
        }
    }
    __syncthreads();

    // ---- prime V chunk 0 (32 rows) via cp.async, overlapping softmax ----
    {
        const int vrow  = tid >> 4;          // 0..15
        const int vseg4 = (tid & 15) << 2;   // 0,4,..,60
        const float* Vg = &g_V[((size_t)(b*SKL))*EMBED + h*HDIM];
        cp_async16_ca(&uni[vrow*VF_PITCH + vseg4],      Vg + (size_t)vrow*EMBED + vseg4);
        cp_async16_ca(&uni[(vrow+16)*VF_PITCH + vseg4], Vg + (size_t)(vrow+16)*EMBED + vseg4);
        cp_commit();
    }

    // ---------------- softmax (each warp: 2 rows of 512) ----------------
    #pragma unroll
    for (int qq = 0; qq < 2; qq++) {
        const int q = qa + qq;
        float x[16];
        #pragma unroll
        for (int j = 0; j < 16; j++) x[j] = scT[(lane + 32*j)*SCT_PITCH + q];
        float m = -1e30f;
        #pragma unroll
        for (int j = 0; j < 16; j++) m = fmaxf(m, x[j]);
        #pragma unroll
        for (int o = 16; o; o >>= 1) m = fmaxf(m, __shfl_xor_sync(0xffffffffu, m, o));
        float s = 0.f;
        #pragma unroll
        for (int j = 0; j < 16; j++) { x[j] = __expf(x[j] - m); s += x[j]; }
        #pragma unroll
        for (int o = 16; o; o >>= 1) s += __shfl_xor_sync(0xffffffffu, s, o);
        const float r = 1.0f / s;
        float* arow = attn_out + ((size_t)((b*HEADS + h)*SQL + q0t + q))*SKL;
        #pragma unroll
        for (int j = 0; j < 16; j++) {
            float p = x[j] * r;
            scT[(lane + 32*j)*SCT_PITCH + q] = p;
            arow[lane + 32*j] = p;
        }
    }

    // ========= AV phase: 16 chunks of 32 k-rows, reg-prefetch =========
    {
        float* kvf = uni;                    // [32][68]
        const int vrow  = tid >> 4;
        const int vseg4 = (tid & 15) << 2;
        const float* Vg = &g_V[((size_t)(b*SKL))*EMBED + h*HDIM];
        const int g  = lane >> 3;            // q-group: q = 4g..4g+3
        const int dl = warp*8 + (lane & 7);  // this thread's d

        cp_wait<0>();
        __syncthreads();                     // chunk 0 resident

        float4 vpre[2];
        float a0=0.f, a1=0.f, a2=0.f, a3=0.f;
        for (int c = 0; c < NCHV; c++) {
            if (c + 1 < NCHV) {
                #pragma unroll
                for (int it = 0; it < 2; it++)
                    vpre[it] = *(const float4*)(Vg + ((size_t)((c+1)*CKV + vrow + it*16))*EMBED + vseg4);
            }
            const float* pb  = &scT[(c*CKV)*SCT_PITCH + 4*g];
            const float* vbp = kvf + dl;
            #pragma unroll 8
            for (int kp = 0; kp < CKV; kp++) {
                float4 p = *(const float4*)(pb + kp*SCT_PITCH);
                float  v = vbp[kp*VF_PITCH];
                a0 += p.x*v; a1 += p.y*v; a2 += p.z*v; a3 += p.w*v;
            }
            __syncthreads();
            if (c + 1 < NCHV) {
                #pragma unroll
                for (int it = 0; it < 2; it++)
                    *(float4*)&kvf[(vrow + it*16)*VF_PITCH + vseg4] = vpre[it];
                __syncthreads();
            }
        }

        float* abase = &g_att[((size_t)(b*SQL + q0t + 4*g))*EMBED + h*HDIM + dl];
        abase[0]       = a0;
        abase[EMBED]   = a1;
        abase[2*EMBED] = a2;
        abase[3*EMBED] = a3;
    }
}

// ---------------------------------------------------------------------------
extern "C" void kernel_launch(void* const* d_in, const int* in_sizes, int n_in,
                              void* d_out, int out_size)
{
    (void)in_sizes; (void)n_in; (void)out_size;
    const float* query = (const float*)d_in[0];
    const float* key_  = (const float*)d_in[1];
    const float* value = (const float*)d_in[2];
    const float* Wq = (const float*)d_in[3];
    const float* bq = (const float*)d_in[4];
    const float* Wk = (const float*)d_in[5];
    const float* bk = (const float*)d_in[6];
    const float* Wv = (const float*)d_in[7];
    const float* bv = (const float*)d_in[8];
    const float* vp = (const float*)d_in[9];
    const float* Wo = (const float*)d_in[10];
    const float* bo = (const float*)d_in[11];

    float* out  = (float*)d_out;                 // [B, SQ, EMBED]
    float* attn = out + (size_t)MTOT * EMBED;    // [B, H, SQ, SK]

    __half *gQh, *gKh;
    float *gV, *gA;
    cudaGetSymbolAddress((void**)&gQh, g_Qh);
    cudaGetSymbolAddress((void**)&gKh, g_Kh);
    cudaGetSymbolAddress((void**)&gV,  g_V);
    cudaGetSymbolAddress((void**)&gA,  g_att);

    const int smem_bytes = ATTN_SMEM_FLOATS * (int)sizeof(float);
    cudaFuncSetAttribute(attn_kernel, cudaFuncAttributeMaxDynamicSharedMemorySize, smem_bytes);

    dim3 ggrid3(EMBED/64, MTOT/64, 3);
    gemm_bias3_kernel<<<ggrid3, 256>>>(query, key_, value,
                                       Wq, Wk, Wv,
                                       bq, bk, bv,
                                       nullptr, nullptr, gV,
                                       gQh, gKh, nullptr,
                                       MTOT, EMBED, EMBED);

    dim3 agrid(SQL/16, HEADS, BATCH);  // (32, 4, 4)
    attn_kernel<<<agrid, 256, smem_bytes>>>(vp, attn);

    dim3 ggrid(EMBED/64, MTOT/64, 1);
    gemm_bias3_kernel<<<ggrid, 256>>>(gA, gA, gA,
                                      Wo, Wo, Wo,
                                      bo, bo, bo,
                                      out, out, out,
                                      nullptr, nullptr, nullptr,
                                      MTOT, EMBED, EMBED);
}

// round 13
// speedup vs baseline: 1.1418x; 1.0091x over previous
#include <cuda_runtime.h>
#include <cuda_fp16.h>
#include <cstdint>

#define EMBED 256
#define HEADS 4
#define HDIM  64
#define BATCH 4
#define SQL   512
#define SKL   512
#define MTOT  (BATCH*SQL)   /* 2048 */

// Scratch (allocation-free rule: __device__ globals)
__device__ __half g_Qh[MTOT*EMBED];   // Q projection, half
__device__ __half g_Kh[MTOT*EMBED];   // K projection, half
__device__ float  g_V [MTOT*EMBED];   // V projection, f32
__device__ float  g_att[MTOT*EMBED];  // attended, f32

__device__ __forceinline__ __half2 htanh2(__half2 x) {
    unsigned int xi = *reinterpret_cast<unsigned int*>(&x);
    unsigned int yi;
    asm("tanh.approx.f16x2 %0, %1;" : "=r"(yi) : "r"(xi));
    return *reinterpret_cast<__half2*>(&yi);
}

// FMA-pipe tanh: odd interpolant on |x|<=2.75 (clamped), t = xc * P(xc^2).
__device__ __forceinline__ __half2 poly_tanh2(__half2 x) {
    const __half2 lo = __float2half2_rn(-2.75f);
    const __half2 hi = __float2half2_rn( 2.75f);
    __half2 xc = __hmax2(lo, __hmin2(x, hi));
    __half2 u  = __hmul2(xc, xc);
    __half2 p  = __hfma2(u, __float2half2_rn(-6.3914e-05f), __float2half2_rn(1.60803e-03f));
    p = __hfma2(u, p, __float2half2_rn(-1.63146e-02f));
    p = __hfma2(u, p, __float2half2_rn( 8.88551e-02f));
    p = __hfma2(u, p, __float2half2_rn(-3.096166e-01f));
    p = __hfma2(u, p, __float2half2_rn( 9.975679e-01f));
    return __hmul2(xc, p);
}

__device__ __forceinline__ __half2 tanh_mixed(__half2 x, bool use_poly) {
    return use_poly ? poly_tanh2(x) : htanh2(x);
}

__device__ __forceinline__ float sumh2(__half2 h) {
    float2 f = __half22float2(h);
    return f.x + f.y;
}
__device__ __forceinline__ __half2 u2h(unsigned int u) {
    return *reinterpret_cast<__half2*>(&u);
}
__device__ __forceinline__ void cp_async16_ca(void* smem_dst, const void* gsrc) {
    unsigned int saddr = (unsigned int)__cvta_generic_to_shared(smem_dst);
    asm volatile("cp.async.ca.shared.global [%0], [%1], 16;\n" :: "r"(saddr), "l"(gsrc));
}
__device__ __forceinline__ void cp_commit() {
    asm volatile("cp.async.commit_group;\n");
}
template<int N>
__device__ __forceinline__ void cp_wait() {
    asm volatile("cp.async.wait_group %0;\n" :: "n"(N));
}

// ---------------------------------------------------------------------------
// C[M,N] = A[M,K] @ W[N,K]^T + bias[N]  (torch Linear). grid.z picks problem;
// Hz != nullptr -> write half to Hz, else f32 to Cz.
// ---------------------------------------------------------------------------
__global__ __launch_bounds__(256) void gemm_bias3_kernel(
    const float* __restrict__ A0, const float* __restrict__ A1, const float* __restrict__ A2,
    const float* __restrict__ W0, const float* __restrict__ W1, const float* __restrict__ W2,
    const float* __restrict__ b0, const float* __restrict__ b1, const float* __restrict__ b2,
    float* __restrict__ C0, float* __restrict__ C1, float* __restrict__ C2,
    __half* __restrict__ H0, __half* __restrict__ H1, __half* __restrict__ H2,
    int M, int N, int K)
{
    const float* A; const float* W; const float* bias; float* C; __half* H;
    if (blockIdx.z == 0)      { A = A0; W = W0; bias = b0; C = C0; H = H0; }
    else if (blockIdx.z == 1) { A = A1; W = W1; bias = b1; C = C1; H = H1; }
    else                      { A = A2; W = W2; bias = b2; C = C2; H = H2; }

    __shared__ float As[2][16][68];
    __shared__ float Ws[2][16][68];
    const int tid = threadIdx.x;
    const int tx  = tid & 15;
    const int ty  = tid >> 4;
    const int n0  = blockIdx.x * 64;
    const int m0  = blockIdx.y * 64;

    const int lr = tid >> 2;
    const int lc = (tid & 3) << 2;
    const float* Ag = A + (size_t)(m0 + lr) * K + lc;
    const float* Wg = W + (size_t)(n0 + lr) * K + lc;

    float a00=0,a01=0,a02=0,a03=0, a10=0,a11=0,a12=0,a13=0;
    float a20=0,a21=0,a22=0,a23=0, a30=0,a31=0,a32=0,a33=0;

    float4 av = *(const float4*)(Ag);
    float4 wv = *(const float4*)(Wg);
    int buf = 0;

    for (int k0 = 0; k0 < K; k0 += 16) {
        As[buf][lc+0][lr] = av.x; As[buf][lc+1][lr] = av.y;
        As[buf][lc+2][lr] = av.z; As[buf][lc+3][lr] = av.w;
        Ws[buf][lc+0][lr] = wv.x; Ws[buf][lc+1][lr] = wv.y;
        Ws[buf][lc+2][lr] = wv.z; Ws[buf][lc+3][lr] = wv.w;
        __syncthreads();
        if (k0 + 16 < K) {
            av = *(const float4*)(Ag + k0 + 16);
            wv = *(const float4*)(Wg + k0 + 16);
        }
        #pragma unroll
        for (int k = 0; k < 16; k++) {
            float4 a = *(const float4*)&As[buf][k][ty*4];
            float4 w = *(const float4*)&Ws[buf][k][tx*4];
            a00 += a.x*w.x; a01 += a.x*w.y; a02 += a.x*w.z; a03 += a.x*w.w;
            a10 += a.y*w.x; a11 += a.y*w.y; a12 += a.y*w.z; a13 += a.y*w.w;
            a20 += a.z*w.x; a21 += a.z*w.y; a22 += a.z*w.z; a23 += a.z*w.w;
            a30 += a.w*w.x; a31 += a.w*w.y; a32 += a.w*w.z; a33 += a.w*w.w;
        }
        buf ^= 1;
    }

    const float4 bb = *(const float4*)&bias[n0 + tx*4];
    float r0x=a00+bb.x, r0y=a01+bb.y, r0z=a02+bb.z, r0w=a03+bb.w;
    float r1x=a10+bb.x, r1y=a11+bb.y, r1z=a12+bb.z, r1w=a13+bb.w;
    float r2x=a20+bb.x, r2y=a21+bb.y, r2z=a22+bb.z, r2w=a23+bb.w;
    float r3x=a30+bb.x, r3y=a31+bb.y, r3z=a32+bb.z, r3w=a33+bb.w;

    if (H) {
        __half* Hp = H + (size_t)(m0 + ty*4) * N + n0 + tx*4;
        __half2 p0, p1;
        p0 = __floats2half2_rn(r0x, r0y); p1 = __floats2half2_rn(r0z, r0w);
        *(uint2*)(Hp)       = make_uint2(*(unsigned int*)&p0, *(unsigned int*)&p1);
        p0 = __floats2half2_rn(r1x, r1y); p1 = __floats2half2_rn(r1z, r1w);
        *(uint2*)(Hp + N)   = make_uint2(*(unsigned int*)&p0, *(unsigned int*)&p1);
        p0 = __floats2half2_rn(r2x, r2y); p1 = __floats2half2_rn(r2z, r2w);
        *(uint2*)(Hp + 2*N) = make_uint2(*(unsigned int*)&p0, *(unsigned int*)&p1);
        p0 = __floats2half2_rn(r3x, r3y); p1 = __floats2half2_rn(r3z, r3w);
        *(uint2*)(Hp + 3*N) = make_uint2(*(unsigned int*)&p0, *(unsigned int*)&p1);
    } else {
        float* Cp = C + (size_t)(m0 + ty*4) * N + n0 + tx*4;
        float4 o;
        o.x=r0x; o.y=r0y; o.z=r0z; o.w=r0w; *(float4*)(Cp)       = o;
        o.x=r1x; o.y=r1y; o.z=r1z; o.w=r1w; *(float4*)(Cp + N)   = o;
        o.x=r2x; o.y=r2y; o.z=r2z; o.w=r2w; *(float4*)(Cp + 2*N) = o;
        o.x=r3x; o.y=r3y; o.z=r3z; o.w=r3w; *(float4*)(Cp + 3*N) = o;
    }
}

// ---------------------------------------------------------------------------
// Fused additive-attention kernel, v10 = v9 with reduced register pressure:
//  * score: CKK=32 (16 chunks), ONE k-row per lane -> 4 accumulators (was 8),
//    single uint4 K prefetch (was 2). Hybrid MUFU/FMA tanh (f=3/8) kept.
//  * AV: unchanged (CKV=32 reg-prefetch, cp.async-primed chunk 0).
// Smem floats: scT 10240 + union 2176 + qh 512 + vh 32 = 51840B -> 4 blk/SM.
// ---------------------------------------------------------------------------
#define SCT_PITCH 20
#define CKK 32
#define NCHK (SKL/CKK)    /* 16 */
#define CKV 32
#define NCHV (SKL/CKV)    /* 16 */
#define VF_PITCH 68
#define UNION_FLOATS 2176
#define ATTN_SMEM_FLOATS (SKL*SCT_PITCH + UNION_FLOATS + 512 + 32)

__global__ __launch_bounds__(256, 4) void attn_kernel(
    const float* __restrict__ vparam, float* __restrict__ attn_out)
{
    extern __shared__ float smem[];
    float*  scT = smem;                           // [512][20]
    float*  uni = scT + SKL*SCT_PITCH;            // union staging
    __half* qh  = (__half*)(uni + UNION_FLOATS);  // [16][64]
    __half* vh  = qh + 16*64;                     // [64]

    const int tid  = threadIdx.x;
    const int lane = tid & 31;
    const int warp = tid >> 5;
    const int b  = blockIdx.z;
    const int h  = blockIdx.y;
    const int q0t = blockIdx.x << 4;

    if (tid < 64) vh[tid] = __float2half(vparam[h*HDIM + tid]);
    {
        int row = tid >> 4;
        int seg = tid & 15;
        const uint2* src = (const uint2*)&g_Qh[((size_t)(b*SQL + q0t + row))*EMBED + h*HDIM + seg*4];
        *(uint2*)&qh[row*64 + seg*4] = *src;
    }

    const float scale = 0.125f;
    const int qa = warp*2;
    const int qb = qa + 1;

    // ====== score phase: 16 chunks of 32 k-rows, 1 k-row/lane, reg-prefetch ==
    {
        __half* kb = (__half*)uni;            // [32 rows][64 halves] swizzled
        const int krow = tid >> 3;            // 0..31
        const int kseg = tid & 7;             // 16B segment of 128B row
        const int sseg = kseg ^ (krow & 7);   // swizzled segment
        const __half* Kg = &g_Kh[((size_t)(b*SKL))*EMBED + h*HDIM];

        uint4 kpre = *(const uint4*)(Kg + (size_t)krow*EMBED + kseg*8);
        *(uint4*)&kb[krow*64 + sseg*8] = kpre;
        __syncthreads();

        for (int c = 0; c < NCHK; c++) {
            if (c + 1 < NCHK)
                kpre = *(const uint4*)(Kg + (size_t)((c+1)*CKK + krow)*EMBED + kseg*8);

            const uint4* qa4p = (const uint4*)&qh[qa*64];
            const uint4* qb4p = (const uint4*)&qh[qb*64];
            const uint4* vv4p = (const uint4*)vh;
            const __half* kr = kb + lane*64;
            const int sw = lane & 7;

            __half2 z = __float2half2_rn(0.f);
            __half2 accA0=z, accA1=z, accB0=z, accB1=z;

            #pragma unroll
            for (int db = 0; db < 8; db++) {
                const bool up = (db == 1) || (db == 4) || (db == 6);  // f=3/8 poly
                uint4 k4  = *(const uint4*)(kr + ((db ^ sw) * 8));
                uint4 qa4 = qa4p[db];
                uint4 qb4 = qb4p[db];
                uint4 vv4 = vv4p[db];

                __half2 k0=u2h(k4.x), k1=u2h(k4.y), k2=u2h(k4.z), k3=u2h(k4.w);
                __half2 qa0=u2h(qa4.x), qa1=u2h(qa4.y), qa2=u2h(qa4.z), qa3=u2h(qa4.w);
                __half2 qb0=u2h(qb4.x), qb1=u2h(qb4.y), qb2=u2h(qb4.z), qb3=u2h(qb4.w);
                __half2 v0=u2h(vv4.x), v1=u2h(vv4.y), v2=u2h(vv4.z), v3=u2h(vv4.w);

                accA0 = __hfma2(v0, tanh_mixed(__hadd2(qa0, k0), up), accA0);
                accB0 = __hfma2(v0, tanh_mixed(__hadd2(qb0, k0), up), accB0);
                accA1 = __hfma2(v1, tanh_mixed(__hadd2(qa1, k1), up), accA1);
                accB1 = __hfma2(v1, tanh_mixed(__hadd2(qb1, k1), up), accB1);
                accA0 = __hfma2(v2, tanh_mixed(__hadd2(qa2, k2), up), accA0);
                accB0 = __hfma2(v2, tanh_mixed(__hadd2(qb2, k2), up), accB0);
                accA1 = __hfma2(v3, tanh_mixed(__hadd2(qa3, k3), up), accA1);
                accB1 = __hfma2(v3, tanh_mixed(__hadd2(qb3, k3), up), accB1);
            }

            scT[(c*CKK + lane)*SCT_PITCH + qa] = (sumh2(accA0) + sumh2(accA1)) * scale;
            scT[(c*CKK + lane)*SCT_PITCH + qb] = (sumh2(accB0) + sumh2(accB1)) * scale;

            __syncthreads();
            if (c + 1 < NCHK) {
                *(uint4*)&kb[krow*64 + sseg*8] = kpre;
                __syncthreads();
            }
        }
    }
    __syncthreads();

    // ---- prime V chunk 0 (32 rows) via cp.async, overlapping softmax ----
    {
        const int vrow  = tid >> 4;          // 0..15
        const int vseg4 = (tid & 15) << 2;   // 0,4,..,60
        const float* Vg = &g_V[((size_t)(b*SKL))*EMBED + h*HDIM];
        cp_async16_ca(&uni[vrow*VF_PITCH + vseg4],      Vg + (size_t)vrow*EMBED + vseg4);
        cp_async16_ca(&uni[(vrow+16)*VF_PITCH + vseg4], Vg + (size_t)(vrow+16)*EMBED + vseg4);
        cp_commit();
    }

    // ---------------- softmax (each warp: 2 rows of 512) ----------------
    #pragma unroll
    for (int qq = 0; qq < 2; qq++) {
        const int q = qa + qq;
        float x[16];
        #pragma unroll
        for (int j = 0; j < 16; j++) x[j] = scT[(lane + 32*j)*SCT_PITCH + q];
        float m = -1e30f;
        #pragma unroll
        for (int j = 0; j < 16; j++) m = fmaxf(m, x[j]);
        #pragma unroll
        for (int o = 16; o; o >>= 1) m = fmaxf(m, __shfl_xor_sync(0xffffffffu, m, o));
        float s = 0.f;
        #pragma unroll
        for (int j = 0; j < 16; j++) { x[j] = __expf(x[j] - m); s += x[j]; }
        #pragma unroll
        for (int o = 16; o; o >>= 1) s += __shfl_xor_sync(0xffffffffu, s, o);
        const float r = 1.0f / s;
        float* arow = attn_out + ((size_t)((b*HEADS + h)*SQL + q0t + q))*SKL;
        #pragma unroll
        for (int j = 0; j < 16; j++) {
            float p = x[j] * r;
            scT[(lane + 32*j)*SCT_PITCH + q] = p;
            arow[lane + 32*j] = p;
        }
    }

    // ========= AV phase: 16 chunks of 32 k-rows, reg-prefetch =========
    {
        float* kvf = uni;                    // [32][68]
        const int vrow  = tid >> 4;
        const int vseg4 = (tid & 15) << 2;
        const float* Vg = &g_V[((size_t)(b*SKL))*EMBED + h*HDIM];
        const int g  = lane >> 3;            // q-group: q = 4g..4g+3
        const int dl = warp*8 + (lane & 7);  // this thread's d

        cp_wait<0>();
        __syncthreads();                     // chunk 0 resident

        float4 vpre[2];
        float a0=0.f, a1=0.f, a2=0.f, a3=0.f;
        for (int c = 0; c < NCHV; c++) {
            if (c + 1 < NCHV) {
                #pragma unroll
                for (int it = 0; it < 2; it++)
                    vpre[it] = *(const float4*)(Vg + ((size_t)((c+1)*CKV + vrow + it*16))*EMBED + vseg4);
            }
            const float* pb  = &scT[(c*CKV)*SCT_PITCH + 4*g];
            const float* vbp = kvf + dl;
            #pragma unroll 8
            for (int kp = 0; kp < CKV; kp++) {
                float4 p = *(const float4*)(pb + kp*SCT_PITCH);
                float  v = vbp[kp*VF_PITCH];
                a0 += p.x*v; a1 += p.y*v; a2 += p.z*v; a3 += p.w*v;
            }
            __syncthreads();
            if (c + 1 < NCHV) {
                #pragma unroll
                for (int it = 0; it < 2; it++)
                    *(float4*)&kvf[(vrow + it*16)*VF_PITCH + vseg4] = vpre[it];
                __syncthreads();
            }
        }

        float* abase = &g_att[((size_t)(b*SQL + q0t + 4*g))*EMBED + h*HDIM + dl];
        abase[0]       = a0;
        abase[EMBED]   = a1;
        abase[2*EMBED] = a2;
        abase[3*EMBED] = a3;
    }
}

// ---------------------------------------------------------------------------
extern "C" void kernel_launch(void* const* d_in, const int* in_sizes, int n_in,
                              void* d_out, int out_size)
{
    (void)in_sizes; (void)n_in; (void)out_size;
    const float* query = (const float*)d_in[0];
    const float* key_  = (const float*)d_in[1];
    const float* value = (const float*)d_in[2];
    const float* Wq = (const float*)d_in[3];
    const float* bq = (const float*)d_in[4];
    const float* Wk = (const float*)d_in[5];
    const float* bk = (const float*)d_in[6];
    const float* Wv = (const float*)d_in[7];
    const float* bv = (const float*)d_in[8];
    const float* vp = (const float*)d_in[9];
    const float* Wo = (const float*)d_in[10];
    const float* bo = (const float*)d_in[11];

    float* out  = (float*)d_out;                 // [B, SQ, EMBED]
    float* attn = out + (size_t)MTOT * EMBED;    // [B, H, SQ, SK]

    __half *gQh, *gKh;
    float *gV, *gA;
    cudaGetSymbolAddress((void**)&gQh, g_Qh);
    cudaGetSymbolAddress((void**)&gKh, g_Kh);
    cudaGetSymbolAddress((void**)&gV,  g_V);
    cudaGetSymbolAddress((void**)&gA,  g_att);

    const int smem_bytes = ATTN_SMEM_FLOATS * (int)sizeof(float);
    cudaFuncSetAttribute(attn_kernel, cudaFuncAttributeMaxDynamicSharedMemorySize, smem_bytes);

    dim3 ggrid3(EMBED/64, MTOT/64, 3);
    gemm_bias3_kernel<<<ggrid3, 256>>>(query, key_, value,
                                       Wq, Wk, Wv,
                                       bq, bk, bv,
                                       nullptr, nullptr, gV,
                                       gQh, gKh, nullptr,
                                       MTOT, EMBED, EMBED);

    dim3 agrid(SQL/16, HEADS, BATCH);  // (32, 4, 4)
    attn_kernel<<<agrid, 256, smem_bytes>>>(vp, attn);

    dim3 ggrid(EMBED/64, MTOT/64, 1);
    gemm_bias3_kernel<<<ggrid, 256>>>(gA, gA, gA,
                                      Wo, Wo, Wo,
                                      bo, bo, bo,
                                      out, out, out,
                                      nullptr, nullptr, nullptr,
                                      MTOT, EMBED, EMBED);
}